// round 2
// baseline (speedup 1.0000x reference)
#include <cuda_runtime.h>
#include <math.h>

// Problem constants
constexpr int B_ = 4, S_ = 4096, D_ = 64;
constexpr float NEGV = -1e9f;
constexpr int BC = 32;   // key cols per tile

// Scratch (allocation-free rule: __device__ globals)
__device__ float g_Q[B_ * S_ * D_];
__device__ float g_K[B_ * S_ * D_];   // K * P_K_emb
__device__ float g_V[B_ * S_ * D_];   // V * P_V_emb
__device__ float g_meanV[B_ * D_];    // fallback for fully-masked rows
__device__ int   g_padkind;           // 0=uint8, 1=int32, 2=float32

// ---------------------------------------------------------------------------
// Kernel 0: detect pad_mask storage dtype. Reads only the first 16384 bytes
// (the minimum possible buffer size). Deterministic for fixed inputs.
//   float32 bool -> bytes contain 0x80 / 0x3F  (>=2)        -> kind 2
//   uint8 bool   -> some byte at idx%4!=0 is nonzero        -> kind 0
//   int32 bool   -> nonzero only at idx%4==0, values 0/1    -> kind 1
// ---------------------------------------------------------------------------
__global__ void detect_pad_kernel(const unsigned char* __restrict__ p)
{
    __shared__ int f[2];
    const int t = threadIdx.x;
    if (t < 2) f[t] = 0;
    __syncthreads();
    int ge2 = 0, odd = 0;
    for (int i = t; i < B_ * S_; i += blockDim.x) {
        unsigned v = p[i];
        if (v >= 2u) ge2 = 1;
        if ((i & 3) && v) odd = 1;
    }
    if (ge2) atomicOr(&f[0], 1);
    if (odd) atomicOr(&f[1], 1);
    __syncthreads();
    if (t == 0) g_padkind = f[0] ? 2 : (f[1] ? 0 : 1);
}

// ---------------------------------------------------------------------------
// Kernel 1: fused QKV projection + popularity modulation.
// One block = 64 rows, one thread = one row. W staged through smem per matrix.
// ---------------------------------------------------------------------------
__global__ __launch_bounds__(64) void proj_kernel(
    const float* __restrict__ E,  const float* __restrict__ PK, const float* __restrict__ PV,
    const float* __restrict__ Wq, const float* __restrict__ bq,
    const float* __restrict__ Wk, const float* __restrict__ bk,
    const float* __restrict__ Wv, const float* __restrict__ bv)
{
    __shared__ float Wsm[D_ * D_];
    const int t = threadIdx.x;
    const size_t g = (size_t)blockIdx.x * 64 + t;

    float4 e[16];
    const float4* Erow = reinterpret_cast<const float4*>(E + g * D_);
    #pragma unroll
    for (int i = 0; i < 16; i++) e[i] = Erow[i];

    const float* Ws[3]  = {Wq, Wk, Wv};
    const float* bsx[3] = {bq, bk, bv};
    float* outg[3]      = {g_Q, g_K, g_V};

    for (int m = 0; m < 3; m++) {
        __syncthreads();
        float4* Wsm4 = reinterpret_cast<float4*>(Wsm);
        const float4* Wg4 = reinterpret_cast<const float4*>(Ws[m]);
        #pragma unroll
        for (int i = 0; i < 16; i++) Wsm4[t + i * 64] = Wg4[t + i * 64];
        __syncthreads();

        float outv[D_];
        for (int c = 0; c < D_; c++) {
            const float4* wr = reinterpret_cast<const float4*>(Wsm + c * D_);
            float a0 = 0.f, a1 = 0.f, a2 = 0.f, a3 = 0.f;
            #pragma unroll
            for (int i = 0; i < 4; i++) {
                float4 w0 = wr[4 * i + 0];
                a0 += e[4 * i + 0].x * w0.x; a0 += e[4 * i + 0].y * w0.y;
                a0 += e[4 * i + 0].z * w0.z; a0 += e[4 * i + 0].w * w0.w;
                float4 w1 = wr[4 * i + 1];
                a1 += e[4 * i + 1].x * w1.x; a1 += e[4 * i + 1].y * w1.y;
                a1 += e[4 * i + 1].z * w1.z; a1 += e[4 * i + 1].w * w1.w;
                float4 w2 = wr[4 * i + 2];
                a2 += e[4 * i + 2].x * w2.x; a2 += e[4 * i + 2].y * w2.y;
                a2 += e[4 * i + 2].z * w2.z; a2 += e[4 * i + 2].w * w2.w;
                float4 w3 = wr[4 * i + 3];
                a3 += e[4 * i + 3].x * w3.x; a3 += e[4 * i + 3].y * w3.y;
                a3 += e[4 * i + 3].z * w3.z; a3 += e[4 * i + 3].w * w3.w;
            }
            outv[c] = bsx[m][c] + ((a0 + a1) + (a2 + a3));
        }

        float4* o4 = reinterpret_cast<float4*>(outg[m] + g * D_);
        if (m == 0) {
            #pragma unroll
            for (int i = 0; i < 16; i++)
                o4[i] = make_float4(outv[4*i], outv[4*i+1], outv[4*i+2], outv[4*i+3]);
        } else {
            const float4* m4 = reinterpret_cast<const float4*>((m == 1 ? PK : PV) + g * D_);
            #pragma unroll
            for (int i = 0; i < 16; i++) {
                float4 mm = m4[i];
                o4[i] = make_float4(outv[4*i] * mm.x, outv[4*i+1] * mm.y,
                                    outv[4*i+2] * mm.z, outv[4*i+3] * mm.w);
            }
        }
    }
}

// ---------------------------------------------------------------------------
// Kernel 2: per-batch mean of V_p (fallback output for fully-masked rows)
// ---------------------------------------------------------------------------
__global__ __launch_bounds__(256) void meanv_kernel()
{
    const int b = blockIdx.x;
    const int t = threadIdx.x;
    const int d = t & 63;
    const int part = t >> 6;

    float acc = 0.f;
    const float* base = g_V + ((size_t)b * S_) * D_ + d;
    for (int s = part * 1024; s < (part + 1) * 1024; s++)
        acc += base[(size_t)s * D_];

    __shared__ float red[256];
    red[t] = acc;
    __syncthreads();
    if (t < 64)
        g_meanV[b * D_ + t] =
            (red[t] + red[t + 64] + red[t + 128] + red[t + 192]) * (1.0f / (float)S_);
}

// ---------------------------------------------------------------------------
// Kernel 3: causal flash attention, fp32, online softmax.
// Block = 128 threads = TWO independent 64-thread halves over the SAME
// 64-row q-tile: half 0 processes even key-tiles, half 1 odd key-tiles
// (qt+1 tiles each -> exactly equal per-warp work), merged at the end.
// 1024 warps total; heavy q-tiles scheduled first.
// ---------------------------------------------------------------------------
__global__ __launch_bounds__(128) void attn_kernel(const void* __restrict__ pad,
                                                   float* __restrict__ out)
{
    const int b  = blockIdx.y;
    const int qt = (gridDim.x - 1) - blockIdx.x;   // heavy blocks first
    const int h  = threadIdx.x >> 6;               // half id: 0 even tiles, 1 odd
    const int t  = threadIdx.x & 63;               // row within q-tile
    const int q  = qt * 64 + t;
    const size_t rowoff = ((size_t)b * S_ + q) * D_;
    const int kind = g_padkind;

    // Q row in registers
    float4 Qr[16];
    const float4* qg = reinterpret_cast<const float4*>(g_Q + rowoff);
    #pragma unroll
    for (int i = 0; i < 16; i++) Qr[i] = qg[i];

    float4 O4[16];
    #pragma unroll
    for (int i = 0; i < 16; i++) O4[i] = make_float4(0.f, 0.f, 0.f, 0.f);
    float mrun = -INFINITY, lrun = 0.f;

    __shared__ float KV[2][2][BC * D_];   // [half][K/V][tile]  32 KB
    __shared__ float pads_s[2][BC];

    const int ntiles = qt + 1;            // tiles per half
    for (int j = 0; j < ntiles; j++) {
        const int kt = (2 * j + h) * BC;

        // half-scoped barrier (2 warps, 64 threads), ids 1 and 2
        asm volatile("bar.sync %0, %1;" :: "r"(1 + h), "r"(64) : "memory");
        {
            const float4* Kg = reinterpret_cast<const float4*>(g_K + ((size_t)b * S_ + kt) * D_);
            const float4* Vg = reinterpret_cast<const float4*>(g_V + ((size_t)b * S_ + kt) * D_);
            float4* Ks4 = reinterpret_cast<float4*>(KV[h][0]);
            float4* Vs4 = reinterpret_cast<float4*>(KV[h][1]);
            #pragma unroll
            for (int i = 0; i < 8; i++) Ks4[t + i * 64] = Kg[t + i * 64];
            #pragma unroll
            for (int i = 0; i < 8; i++) Vs4[t + i * 64] = Vg[t + i * 64];
            if (t < BC) {
                const int idx = b * S_ + kt + t;
                float pv;
                if (kind == 0)      pv = (float)((const unsigned char*)pad)[idx];
                else if (kind == 1) pv = (float)((const int*)pad)[idx];
                else                pv = ((const float*)pad)[idx];
                pads_s[h][t] = pv;
            }
        }
        asm volatile("bar.sync %0, %1;" :: "r"(1 + h), "r"(64) : "memory");

        // ---- scores: s[c] = Q . K[c] ----
        float s[BC];
        #pragma unroll
        for (int c = 0; c < BC; c++) s[c] = 0.f;
        const float4* K4 = reinterpret_cast<const float4*>(KV[h][0]);
        #pragma unroll
        for (int d4 = 0; d4 < 16; d4++) {
            const float4 qv = Qr[d4];
            #pragma unroll
            for (int c = 0; c < BC; c++) {
                float4 kv = K4[c * 16 + d4];
                s[c] += qv.x * kv.x; s[c] += qv.y * kv.y;
                s[c] += qv.z * kv.z; s[c] += qv.w * kv.w;
            }
        }

        // ---- mask + scale, tile max ----
        float mt = -INFINITY;
        #pragma unroll
        for (int c = 0; c < BC; c++) {
            const int kg = kt + c;
            const bool msk = (kg > q) || (pads_s[h][c] != 0.f);
            s[c] = msk ? NEGV : s[c] * 0.125f;   // 1/sqrt(64)
            mt = fmaxf(mt, s[c]);
        }

        // ---- online softmax update ----
        const float mnew = fmaxf(mrun, mt);
        const float corr = __expf(mrun - mnew);
        float lsum = 0.f;
        #pragma unroll
        for (int c = 0; c < BC; c++) {
            s[c] = __expf(s[c] - mnew);
            lsum += s[c];
        }
        lrun = lrun * corr + lsum;
        mrun = mnew;
        #pragma unroll
        for (int i = 0; i < 16; i++) {
            O4[i].x *= corr; O4[i].y *= corr; O4[i].z *= corr; O4[i].w *= corr;
        }

        // ---- O += p . V ----
        const float4* V4 = reinterpret_cast<const float4*>(KV[h][1]);
        #pragma unroll
        for (int c = 0; c < BC; c++) {
            const float pc = s[c];
            #pragma unroll
            for (int d4 = 0; d4 < 16; d4++) {
                float4 vv = V4[c * 16 + d4];
                O4[d4].x += pc * vv.x; O4[d4].y += pc * vv.y;
                O4[d4].z += pc * vv.z; O4[d4].w += pc * vv.w;
            }
        }
    }

    // ---- merge the two halves (overlay scratch on the K/V smem) ----
    __syncthreads();
    float* M = &KV[0][0][0];                 // 64 rows x 68 floats = 17.4 KB
    if (h == 1) {
        float* row = M + t * 68;
        float4* r4 = reinterpret_cast<float4*>(row);
        #pragma unroll
        for (int i = 0; i < 16; i++) r4[i] = O4[i];
        row[64] = mrun;
        row[65] = lrun;
    }
    __syncthreads();
    if (h == 0) {
        const float* row = M + t * 68;
        const float m1 = row[64], l1 = row[65];
        const float mnew = fmaxf(mrun, m1);
        const float c0 = __expf(mrun - mnew);
        const float c1 = __expf(m1 - mnew);
        const float l  = lrun * c0 + l1 * c1;
        const float inv = 1.0f / l;
        const bool allmask = (mnew == NEGV);

        const float4* r4 = reinterpret_cast<const float4*>(row);
        float4* og = reinterpret_cast<float4*>(out + rowoff);
        const float4* mv = reinterpret_cast<const float4*>(g_meanV + b * D_);
        #pragma unroll
        for (int i = 0; i < 16; i++) {
            float4 o1 = r4[i];
            float4 r;
            if (allmask) {
                r = mv[i];
            } else {
                r = make_float4((O4[i].x * c0 + o1.x * c1) * inv,
                                (O4[i].y * c0 + o1.y * c1) * inv,
                                (O4[i].z * c0 + o1.z * c1) * inv,
                                (O4[i].w * c0 + o1.w * c1) * inv);
            }
            og[i] = r;
        }
    }
}

// ---------------------------------------------------------------------------
extern "C" void kernel_launch(void* const* d_in, const int* in_sizes, int n_in,
                              void* d_out, int out_size)
{
    const float* E  = (const float*)d_in[0];
    const float* PK = (const float*)d_in[1];
    const float* PV = (const float*)d_in[2];
    const float* Wq = (const float*)d_in[3];
    const float* bq = (const float*)d_in[4];
    const float* Wk = (const float*)d_in[5];
    const float* bk = (const float*)d_in[6];
    const float* Wv = (const float*)d_in[7];
    const float* bv = (const float*)d_in[8];
    const void*  pad = d_in[9];
    float* out = (float*)d_out;

    detect_pad_kernel<<<1, 1024>>>((const unsigned char*)pad);
    proj_kernel<<<B_ * S_ / 64, 64>>>(E, PK, PV, Wq, bq, Wk, bk, Wv, bv);
    meanv_kernel<<<B_, 256>>>();
    attn_kernel<<<dim3(S_ / 64, B_), 128>>>(pad, out);
}

// round 3
// speedup vs baseline: 1.8514x; 1.8514x over previous
#include <cuda_runtime.h>
#include <math.h>

// Problem constants
constexpr int B_ = 4, S_ = 4096, D_ = 64;
constexpr float NEGV = -1e9f;
constexpr int BC = 32;     // key cols per tile
constexpr int NQ = 4;      // key-range quarters per block

// Scratch (allocation-free rule: __device__ globals)
__device__ float g_Q[B_ * S_ * D_];
__device__ float g_K[B_ * S_ * D_];     // K * P_K_emb
__device__ float g_V[B_ * S_ * D_];     // V * P_V_emb
__device__ float g_part[64][D_];        // meanV partials
__device__ float g_meanV[B_ * D_];      // fallback for fully-masked rows
__device__ int   g_padkind;             // 0=uint8, 1=int32, 2=float32

// ---- packed f32x2 helpers (sm_103a FFMA2) ----
using u64_t = unsigned long long;
__device__ __forceinline__ u64_t fma2(u64_t a, u64_t b, u64_t c) {
    u64_t d; asm("fma.rn.f32x2 %0, %1, %2, %3;" : "=l"(d) : "l"(a), "l"(b), "l"(c)); return d;
}
__device__ __forceinline__ u64_t mul2(u64_t a, u64_t b) {
    u64_t d; asm("mul.rn.f32x2 %0, %1, %2;" : "=l"(d) : "l"(a), "l"(b)); return d;
}
__device__ __forceinline__ u64_t pack2(float lo, float hi) {
    u64_t d; asm("mov.b64 %0, {%1, %2};" : "=l"(d) : "f"(lo), "f"(hi)); return d;
}
__device__ __forceinline__ float2 unpack2(u64_t v) {
    float2 r; asm("mov.b64 {%0, %1}, %2;" : "=f"(r.x), "=f"(r.y) : "l"(v)); return r;
}

// ---------------------------------------------------------------------------
// Kernel 0: detect pad_mask storage dtype (reads first 16384 bytes only).
// ---------------------------------------------------------------------------
__global__ void detect_pad_kernel(const unsigned char* __restrict__ p)
{
    __shared__ int f[2];
    const int t = threadIdx.x;
    if (t < 2) f[t] = 0;
    __syncthreads();
    int ge2 = 0, odd = 0;
    for (int i = t; i < B_ * S_; i += blockDim.x) {
        unsigned v = p[i];
        if (v >= 2u) ge2 = 1;
        if ((i & 3) && v) odd = 1;
    }
    if (ge2) atomicOr(&f[0], 1);
    if (odd) atomicOr(&f[1], 1);
    __syncthreads();
    if (t == 0) g_padkind = f[0] ? 2 : (f[1] ? 0 : 1);
}

// ---------------------------------------------------------------------------
// Kernel 1: fused QKV projection + popularity modulation.
// 64 blocks x 256 threads, one row/thread; all 3 W matrices staged once.
// ---------------------------------------------------------------------------
__global__ __launch_bounds__(256) void proj_kernel(
    const float* __restrict__ E,  const float* __restrict__ PK, const float* __restrict__ PV,
    const float* __restrict__ Wq, const float* __restrict__ bq,
    const float* __restrict__ Wk, const float* __restrict__ bk,
    const float* __restrict__ Wv, const float* __restrict__ bv)
{
    __shared__ float Wsm[3][D_ * D_];     // 48 KB
    const int t = threadIdx.x;
    const size_t g = (size_t)blockIdx.x * 256 + t;

    {
        const float* Ws[3] = {Wq, Wk, Wv};
        #pragma unroll
        for (int m = 0; m < 3; m++) {
            float4* dst = reinterpret_cast<float4*>(Wsm[m]);
            const float4* src = reinterpret_cast<const float4*>(Ws[m]);
            #pragma unroll
            for (int i = 0; i < 4; i++) dst[t + i * 256] = src[t + i * 256];
        }
    }
    __syncthreads();

    // E row packed as f32x2 pairs
    u64_t e2[32];
    {
        const ulonglong2* er = reinterpret_cast<const ulonglong2*>(E + g * D_);
        #pragma unroll
        for (int i = 0; i < 16; i++) { ulonglong2 v = er[i]; e2[2*i] = v.x; e2[2*i+1] = v.y; }
    }

    const float* bsx[3] = {bq, bk, bv};
    float* outg[3]      = {g_Q, g_K, g_V};

    #pragma unroll
    for (int m = 0; m < 3; m++) {
        float outv[D_];
        for (int c = 0; c < D_; c++) {
            const ulonglong2* wr = reinterpret_cast<const ulonglong2*>(Wsm[m] + c * D_);
            u64_t a0 = 0ull, a1 = 0ull;
            #pragma unroll
            for (int d8 = 0; d8 < 16; d8++) {
                ulonglong2 w = wr[d8];
                a0 = fma2(e2[2*d8],   w.x, a0);
                a1 = fma2(e2[2*d8+1], w.y, a1);
            }
            float2 p0 = unpack2(a0), p1 = unpack2(a1);
            outv[c] = bsx[m][c] + ((p0.x + p0.y) + (p1.x + p1.y));
        }
        float4* o4 = reinterpret_cast<float4*>(outg[m] + g * D_);
        if (m == 0) {
            #pragma unroll
            for (int i = 0; i < 16; i++)
                o4[i] = make_float4(outv[4*i], outv[4*i+1], outv[4*i+2], outv[4*i+3]);
        } else {
            const float4* m4 = reinterpret_cast<const float4*>((m == 1 ? PK : PV) + g * D_);
            #pragma unroll
            for (int i = 0; i < 16; i++) {
                float4 mm = m4[i];
                o4[i] = make_float4(outv[4*i] * mm.x, outv[4*i+1] * mm.y,
                                    outv[4*i+2] * mm.z, outv[4*i+3] * mm.w);
            }
        }
    }
}

// ---------------------------------------------------------------------------
// Kernel 2a/2b: per-batch mean of V_p (two-stage, deterministic)
// ---------------------------------------------------------------------------
__global__ __launch_bounds__(256) void meanv1_kernel()
{
    const int blk = blockIdx.x;            // 0..63, 16 per batch
    const int t = threadIdx.x;
    const int d = t & 63;
    const int part = t >> 6;               // 4 parts of 64 rows
    float acc = 0.f;
    const float* base = g_V + ((size_t)blk * 256 + part * 64) * D_ + d;
    for (int i = 0; i < 64; i++) acc += base[(size_t)i * D_];
    __shared__ float red[256];
    red[t] = acc;
    __syncthreads();
    if (t < 64)
        g_part[blk][t] = red[t] + red[t + 64] + red[t + 128] + red[t + 192];
}

__global__ void meanv2_kernel()
{
    const int t = threadIdx.x;             // 256
    const int b = t >> 6, d = t & 63;
    float a = 0.f;
    #pragma unroll
    for (int i = 0; i < 16; i++) a += g_part[b * 16 + i][d];
    g_meanV[b * 64 + d] = a * (1.0f / (float)S_);
}

// ---------------------------------------------------------------------------
// Kernel 3: causal flash attention, fp32 via packed f32x2.
// Block = 256 threads = 4 quarters of 64 threads; each quarter owns every
// 4th key-tile of the SAME 64-row q-tile (1 thread = 1 q-row).
// Each block handles the complementary q-tile pair (qt, 63-qt): exactly
// 130 key-tiles per block -> perfect balance, single wave of 128 blocks.
// ---------------------------------------------------------------------------
__global__ __launch_bounds__(256, 1) void attn_kernel(const void* __restrict__ pad,
                                                      float* __restrict__ out)
{
    extern __shared__ float sm[];
    const int b = blockIdx.y;
    const int t = threadIdx.x & 63;        // q-row within tile
    const int h = threadIdx.x >> 6;        // quarter id
    const int kind = g_padkind;

    float* Kt   = sm + h * (2 * BC * D_);
    float* Vt   = Kt + BC * D_;
    float* padq = sm + NQ * 2 * BC * D_ + h * BC;
    float* M    = sm;                      // merge overlay (reuses tile smem)

    #pragma unroll 1
    for (int phase = 0; phase < 2; phase++) {
        const int qt = phase ? (63 - blockIdx.x) : blockIdx.x;
        const int q  = qt * 64 + t;
        const size_t rowoff = ((size_t)b * S_ + q) * D_;

        __syncthreads();   // previous phase's merge reads done; smem reusable

        // Q row packed
        u64_t Q2[32];
        {
            const ulonglong2* qg = reinterpret_cast<const ulonglong2*>(g_Q + rowoff);
            #pragma unroll
            for (int i = 0; i < 16; i++) { ulonglong2 v = qg[i]; Q2[2*i] = v.x; Q2[2*i+1] = v.y; }
        }
        u64_t O2[32];
        #pragma unroll
        for (int i = 0; i < 32; i++) O2[i] = 0ull;
        float mrun = -INFINITY, lrun = 0.f;

        const int T = 2 * (qt + 1);        // 32-key tiles for this q-tile
        for (int jt = h; jt < T; jt += NQ) {
            const int kt = jt * BC;

            asm volatile("bar.sync %0, %1;" :: "r"(1 + h), "r"(64) : "memory");
            {
                const float4* Kg = reinterpret_cast<const float4*>(g_K + ((size_t)b * S_ + kt) * D_);
                const float4* Vg = reinterpret_cast<const float4*>(g_V + ((size_t)b * S_ + kt) * D_);
                float4* K4 = reinterpret_cast<float4*>(Kt);
                float4* V4 = reinterpret_cast<float4*>(Vt);
                #pragma unroll
                for (int i = 0; i < 8; i++) K4[t + i * 64] = Kg[t + i * 64];
                #pragma unroll
                for (int i = 0; i < 8; i++) V4[t + i * 64] = Vg[t + i * 64];
                if (t < BC) {
                    const int idx = b * S_ + kt + t;
                    float pv;
                    if (kind == 0)      pv = (float)((const unsigned char*)pad)[idx];
                    else if (kind == 1) pv = (float)((const int*)pad)[idx];
                    else                pv = ((const float*)pad)[idx];
                    padq[t] = pv;
                }
            }
            asm volatile("bar.sync %0, %1;" :: "r"(1 + h), "r"(64) : "memory");

            // ---- scores (two halves of 16 cols to bound live registers) ----
            float s[BC];
            const ulonglong2* K2 = reinterpret_cast<const ulonglong2*>(Kt);
            #pragma unroll
            for (int half = 0; half < 2; half++) {
                u64_t s2[16];
                #pragma unroll
                for (int c = 0; c < 16; c++) s2[c] = 0ull;
                #pragma unroll
                for (int d8 = 0; d8 < 16; d8++) {
                    const u64_t qa = Q2[2*d8], qb = Q2[2*d8+1];
                    #pragma unroll
                    for (int c = 0; c < 16; c++) {
                        ulonglong2 kv = K2[(half * 16 + c) * 16 + d8];
                        s2[c] = fma2(qa, kv.x, s2[c]);
                        s2[c] = fma2(qb, kv.y, s2[c]);
                    }
                }
                #pragma unroll
                for (int c = 0; c < 16; c++) {
                    float2 p = unpack2(s2[c]);
                    s[half * 16 + c] = (p.x + p.y) * 0.125f;   // 1/sqrt(64)
                }
            }

            // ---- mask + tile max ----
            float mt = -INFINITY;
            #pragma unroll
            for (int c = 0; c < BC; c++) {
                const bool msk = (kt + c > q) || (padq[c] != 0.f);
                s[c] = msk ? NEGV : s[c];
                mt = fmaxf(mt, s[c]);
            }

            // ---- online softmax ----
            const float mnew = fmaxf(mrun, mt);
            const float corr = __expf(mrun - mnew);
            float lsum = 0.f;
            #pragma unroll
            for (int c = 0; c < BC; c++) {
                s[c] = __expf(s[c] - mnew);
                lsum += s[c];
            }
            lrun = lrun * corr + lsum;
            mrun = mnew;
            const u64_t c2 = pack2(corr, corr);
            #pragma unroll
            for (int i = 0; i < 32; i++) O2[i] = mul2(O2[i], c2);

            // ---- O += p . V ----
            const ulonglong2* V2s = reinterpret_cast<const ulonglong2*>(Vt);
            #pragma unroll
            for (int c = 0; c < BC; c++) {
                const u64_t p2 = pack2(s[c], s[c]);
                #pragma unroll
                for (int d8 = 0; d8 < 16; d8++) {
                    ulonglong2 vv = V2s[c * 16 + d8];
                    O2[2*d8]   = fma2(p2, vv.x, O2[2*d8]);
                    O2[2*d8+1] = fma2(p2, vv.y, O2[2*d8+1]);
                }
            }
        }

        // ---- 4-way merge through smem (overlay on tile area) ----
        __syncthreads();
        if (h != 0) {
            float* row = M + ((h - 1) * 64 + t) * 66;
            #pragma unroll
            for (int i = 0; i < 32; i++) {
                float2 p = unpack2(O2[i]);
                row[2*i] = p.x; row[2*i+1] = p.y;
            }
            row[64] = mrun;
            row[65] = lrun;
        }
        __syncthreads();
        if (h == 0) {
            const float* r1 = M + (0 * 64 + t) * 66;
            const float* r2 = M + (1 * 64 + t) * 66;
            const float* r3 = M + (2 * 64 + t) * 66;
            const float m1 = r1[64], m2 = r2[64], m3 = r3[64];
            const float l1 = r1[65], l2 = r2[65], l3 = r3[65];
            float mx = fmaxf(fmaxf(mrun, m1), fmaxf(m2, m3));
            const float c0 = __expf(mrun - mx);
            const float c1 = __expf(m1 - mx);
            const float c2_ = __expf(m2 - mx);
            const float c3 = __expf(m3 - mx);
            const float lt = lrun * c0 + l1 * c1 + l2 * c2_ + l3 * c3;
            const float inv = 1.0f / lt;
            const bool allmask = (mx == NEGV);

            float4* og = reinterpret_cast<float4*>(out + rowoff);
            const float4* mv = reinterpret_cast<const float4*>(g_meanV + b * D_);
            #pragma unroll
            for (int i = 0; i < 16; i++) {
                float4 r;
                if (allmask) {
                    r = mv[i];
                } else {
                    float2 pa = unpack2(O2[2*i]);
                    float2 pb = unpack2(O2[2*i+1]);
                    r.x = (pa.x * c0 + r1[4*i+0] * c1 + r2[4*i+0] * c2_ + r3[4*i+0] * c3) * inv;
                    r.y = (pa.y * c0 + r1[4*i+1] * c1 + r2[4*i+1] * c2_ + r3[4*i+1] * c3) * inv;
                    r.z = (pb.x * c0 + r1[4*i+2] * c1 + r2[4*i+2] * c2_ + r3[4*i+2] * c3) * inv;
                    r.w = (pb.y * c0 + r1[4*i+3] * c1 + r2[4*i+3] * c2_ + r3[4*i+3] * c3) * inv;
                }
                og[i] = r;
            }
        }
    }
}

// ---------------------------------------------------------------------------
extern "C" void kernel_launch(void* const* d_in, const int* in_sizes, int n_in,
                              void* d_out, int out_size)
{
    const float* E  = (const float*)d_in[0];
    const float* PK = (const float*)d_in[1];
    const float* PV = (const float*)d_in[2];
    const float* Wq = (const float*)d_in[3];
    const float* bq = (const float*)d_in[4];
    const float* Wk = (const float*)d_in[5];
    const float* bk = (const float*)d_in[6];
    const float* Wv = (const float*)d_in[7];
    const float* bv = (const float*)d_in[8];
    const void*  pad = d_in[9];
    float* out = (float*)d_out;

    constexpr int ATTN_SMEM = (NQ * 2 * BC * D_ + NQ * BC) * (int)sizeof(float); // 66048
    cudaFuncSetAttribute(attn_kernel, cudaFuncAttributeMaxDynamicSharedMemorySize, ATTN_SMEM);

    detect_pad_kernel<<<1, 1024>>>((const unsigned char*)pad);
    proj_kernel<<<B_ * S_ / 256, 256>>>(E, PK, PV, Wq, bq, Wk, bk, Wv, bv);
    meanv1_kernel<<<64, 256>>>();
    meanv2_kernel<<<1, 256>>>();
    attn_kernel<<<dim3(32, B_), 256, ATTN_SMEM>>>(pad, out);
}

// round 5
// speedup vs baseline: 4.0171x; 2.1698x over previous
#include <cuda_runtime.h>
#include <cuda_bf16.h>
#include <math.h>
#include <stdint.h>

// Problem constants
constexpr int B_ = 4, S_ = 4096, D_ = 64;
constexpr int MT = 64;            // q rows per tile (one phase)
constexpr int NT = 128;           // keys per k-tile

// ---- global scratch (allocation-free rule) ----
__device__ __align__(16) __nv_bfloat16 g_Qhi[B_*S_*D_], g_Qlo[B_*S_*D_];
__device__ __align__(16) __nv_bfloat16 g_Khi[B_*S_*D_], g_Klo[B_*S_*D_];
__device__ __align__(16) __nv_bfloat16 g_Vhi[B_*S_*D_], g_Vlo[B_*S_*D_];
__device__ float g_part[64][D_];
__device__ float g_meanV[B_*D_];
__device__ int   g_padkind;       // 0=uint8, 1=int32, 2=float32

// ---- f32x2 helpers (proj kernel) ----
using u64_t = unsigned long long;
__device__ __forceinline__ u64_t fma2(u64_t a, u64_t b, u64_t c) {
    u64_t d; asm("fma.rn.f32x2 %0, %1, %2, %3;" : "=l"(d) : "l"(a), "l"(b), "l"(c)); return d;
}
__device__ __forceinline__ float2 unpack2(u64_t v) {
    float2 r; asm("mov.b64 {%0, %1}, %2;" : "=f"(r.x), "=f"(r.y) : "l"(v)); return r;
}

__device__ __forceinline__ uint32_t smem_u32(const void* p) {
    uint32_t a;
    asm("{ .reg .u64 t; cvta.to.shared.u64 t, %1; cvt.u32.u64 %0, t; }" : "=r"(a) : "l"(p));
    return a;
}

// ---- mma.sync helpers (sm_80-compatible PTX; tensor pipe on sm_103) ----
__device__ __forceinline__ void ldm_x4(uint32_t* r, uint32_t a) {
    asm volatile("ldmatrix.sync.aligned.m8n8.x4.shared.b16 {%0,%1,%2,%3}, [%4];"
                 : "=r"(r[0]), "=r"(r[1]), "=r"(r[2]), "=r"(r[3]) : "r"(a));
}
__device__ __forceinline__ void ldm_x4_t(uint32_t* r, uint32_t a) {
    asm volatile("ldmatrix.sync.aligned.m8n8.x4.trans.shared.b16 {%0,%1,%2,%3}, [%4];"
                 : "=r"(r[0]), "=r"(r[1]), "=r"(r[2]), "=r"(r[3]) : "r"(a));
}
__device__ __forceinline__ void mma_bf16(float* c, const uint32_t* a, const uint32_t* b) {
    asm volatile("mma.sync.aligned.m16n8k16.row.col.f32.bf16.bf16.f32 "
                 "{%0,%1,%2,%3}, {%4,%5,%6,%7}, {%8,%9}, {%0,%1,%2,%3};"
                 : "+f"(c[0]), "+f"(c[1]), "+f"(c[2]), "+f"(c[3])
                 : "r"(a[0]), "r"(a[1]), "r"(a[2]), "r"(a[3]), "r"(b[0]), "r"(b[1]));
}
__device__ __forceinline__ uint32_t bfpack(__nv_bfloat16 a, __nv_bfloat16 b) {
    return (uint32_t)__bfloat16_as_ushort(a) | ((uint32_t)__bfloat16_as_ushort(b) << 16);
}

// ---------------------------------------------------------------------------
// Kernel 0: detect pad_mask storage dtype (reads first 16384 bytes only).
// ---------------------------------------------------------------------------
__global__ void detect_pad_kernel(const unsigned char* __restrict__ p)
{
    __shared__ int f[2];
    const int t = threadIdx.x;
    if (t < 2) f[t] = 0;
    __syncthreads();
    int ge2 = 0, odd = 0;
    for (int i = t; i < B_ * S_; i += blockDim.x) {
        unsigned v = p[i];
        if (v >= 2u) ge2 = 1;
        if ((i & 3) && v) odd = 1;
    }
    if (ge2) atomicOr(&f[0], 1);
    if (odd) atomicOr(&f[1], 1);
    __syncthreads();
    if (t == 0) g_padkind = f[0] ? 2 : (f[1] ? 0 : 1);
}

// ---------------------------------------------------------------------------
// Kernel 1: fused QKV projection + popularity modulation + bf16 hi/lo split.
// ---------------------------------------------------------------------------
__global__ __launch_bounds__(256) void proj_kernel(
    const float* __restrict__ E,  const float* __restrict__ PK, const float* __restrict__ PV,
    const float* __restrict__ Wq, const float* __restrict__ bq,
    const float* __restrict__ Wk, const float* __restrict__ bk,
    const float* __restrict__ Wv, const float* __restrict__ bv)
{
    __shared__ float Wsm[3][D_ * D_];
    const int t = threadIdx.x;
    const size_t g = (size_t)blockIdx.x * 256 + t;

    {
        const float* Ws[3] = {Wq, Wk, Wv};
        #pragma unroll
        for (int m = 0; m < 3; m++) {
            float4* dst = reinterpret_cast<float4*>(Wsm[m]);
            const float4* src = reinterpret_cast<const float4*>(Ws[m]);
            #pragma unroll
            for (int i = 0; i < 4; i++) dst[t + i * 256] = src[t + i * 256];
        }
    }
    __syncthreads();

    u64_t e2[32];
    {
        const ulonglong2* er = reinterpret_cast<const ulonglong2*>(E + g * D_);
        #pragma unroll
        for (int i = 0; i < 16; i++) { ulonglong2 v = er[i]; e2[2*i] = v.x; e2[2*i+1] = v.y; }
    }

    const float* bsx[3] = {bq, bk, bv};
    __nv_bfloat16* ohi[3] = {g_Qhi, g_Khi, g_Vhi};
    __nv_bfloat16* olo[3] = {g_Qlo, g_Klo, g_Vlo};

    #pragma unroll
    for (int m = 0; m < 3; m++) {
        float outv[D_];
        for (int c = 0; c < D_; c++) {
            const ulonglong2* wr = reinterpret_cast<const ulonglong2*>(Wsm[m] + c * D_);
            u64_t a0 = 0ull, a1 = 0ull;
            #pragma unroll
            for (int d8 = 0; d8 < 16; d8++) {
                ulonglong2 w = wr[d8];
                a0 = fma2(e2[2*d8],   w.x, a0);
                a1 = fma2(e2[2*d8+1], w.y, a1);
            }
            float2 p0 = unpack2(a0), p1 = unpack2(a1);
            outv[c] = bsx[m][c] + ((p0.x + p0.y) + (p1.x + p1.y));
        }
        if (m > 0) {
            const float* mod = (m == 1 ? PK : PV) + g * D_;
            #pragma unroll
            for (int c = 0; c < D_; c++) outv[c] *= mod[c];
        }
        unsigned short hib[D_], lob[D_];
        #pragma unroll
        for (int c = 0; c < D_; c++) {
            __nv_bfloat16 h = __float2bfloat16_rn(outv[c]);
            float rest = outv[c] - __bfloat162float(h);
            __nv_bfloat16 l = __float2bfloat16_rn(rest);
            hib[c] = __bfloat16_as_ushort(h);
            lob[c] = __bfloat16_as_ushort(l);
        }
        uint4* oh = reinterpret_cast<uint4*>(ohi[m] + g * D_);
        uint4* ol = reinterpret_cast<uint4*>(olo[m] + g * D_);
        const uint4* sh = reinterpret_cast<const uint4*>(hib);
        const uint4* sl = reinterpret_cast<const uint4*>(lob);
        #pragma unroll
        for (int i = 0; i < 8; i++) { oh[i] = sh[i]; ol[i] = sl[i]; }
    }
}

// ---------------------------------------------------------------------------
// Kernel 2a/2b: per-batch mean of V_p (fallback for fully-masked rows)
// ---------------------------------------------------------------------------
__global__ __launch_bounds__(256) void meanv1_kernel()
{
    const int blk = blockIdx.x;
    const int t = threadIdx.x;
    const int d = t & 63;
    const int part = t >> 6;
    float acc = 0.f;
    const __nv_bfloat16* bh = g_Vhi + ((size_t)blk * 256 + part * 64) * D_ + d;
    const __nv_bfloat16* bl = g_Vlo + ((size_t)blk * 256 + part * 64) * D_ + d;
    for (int i = 0; i < 64; i++)
        acc += __bfloat162float(bh[(size_t)i * D_]) + __bfloat162float(bl[(size_t)i * D_]);
    __shared__ float red[256];
    red[t] = acc;
    __syncthreads();
    if (t < 64)
        g_part[blk][t] = red[t] + red[t + 64] + red[t + 128] + red[t + 192];
}

__global__ void meanv2_kernel()
{
    const int t = threadIdx.x;
    const int b = t >> 6, d = t & 63;
    float a = 0.f;
    #pragma unroll
    for (int i = 0; i < 16; i++) a += g_part[b * 16 + i][d];
    g_meanV[b * 64 + d] = a * (1.0f / (float)S_);
}

// ---------------------------------------------------------------------------
// Kernel 3: mma.sync bf16 hi/lo flash attention (no-max softmax).
// CTA = 256 threads = 4 row-warps x 2 key-halves over a 64-row q-tile.
// Pair scheduling (qt, 63-qt): exactly 33 k-tiles per CTA. Scores and P stay
// in register fragments (FA2 C->A fragment identity); key halves merge by ADD.
// ---------------------------------------------------------------------------
constexpr int SM_QHI = 0;                       // 64 x 128B
constexpr int SM_QLO = 8192;
constexpr int SM_KHI = 16384;                   // 128 x 128B
constexpr int SM_KLO = 32768;
constexpr int SM_VHI = 49152;
constexpr int SM_VLO = 65536;
constexpr int SM_PAD = 81920;                   // 128 f32
constexpr int SM_LSM = 82432;                   // 2 x 64 f32
constexpr int SM_MRG = 82944;                   // 64 x 64 f32
constexpr int SM_TOTAL = SM_MRG + 16384;        // 99328

// stage a [rows x 64] bf16 tile into smem, 16B chunks swizzled by chunk^row
__device__ __forceinline__ void stage(uint32_t dst, const __nv_bfloat16* __restrict__ src,
                                      int tid, int iters)
{
    const uint4* s = reinterpret_cast<const uint4*>(src);
    #pragma unroll
    for (int it = 0; it < iters; it++) {
        int i = tid + it * 256;
        uint4 v = s[i];
        int row = i >> 3, c = i & 7;
        uint32_t a = dst + row * 128 + (((uint32_t)(c ^ (row & 7))) << 4);
        asm volatile("st.shared.v4.b32 [%0], {%1,%2,%3,%4};"
                     :: "r"(a), "r"(v.x), "r"(v.y), "r"(v.z), "r"(v.w));
    }
}

__global__ __launch_bounds__(256, 1) void attn_mma_kernel(const void* __restrict__ pad,
                                                          float* __restrict__ out)
{
    extern __shared__ char sm[];
    const uint32_t smb = smem_u32(sm);
    const int tid = threadIdx.x, wid = tid >> 5, lane = tid & 31;
    const int wr = wid & 3, wc = wid >> 2;        // row-warp, key-half
    const int b = blockIdx.y, kind = g_padkind;
    const int g8 = lane >> 3, l8 = lane & 7, l4 = lane >> 2, lq = lane & 3;
    float* padf = reinterpret_cast<float*>(sm + SM_PAD);
    float* lsm  = reinterpret_cast<float*>(sm + SM_LSM);
    float* mrg  = reinterpret_cast<float*>(sm + SM_MRG);

    #pragma unroll 1
    for (int phase = 0; phase < 2; phase++) {
        const int qt = phase ? (63 - blockIdx.x) : blockIdx.x;
        const int qbase = qt * MT;

        __syncthreads();
        stage(smb + SM_QHI, g_Qhi + ((size_t)b * S_ + qbase) * D_, tid, 2);
        stage(smb + SM_QLO, g_Qlo + ((size_t)b * S_ + qbase) * D_, tid, 2);
        __syncthreads();

        // Q A-fragments (hi/lo), 4 d-chunks of 16
        uint32_t qh[4][4], ql[4][4];
        {
            const int row = wr * 16 + (g8 & 1) * 8 + l8;
            #pragma unroll
            for (int dc = 0; dc < 4; dc++) {
                const int c = 2 * dc + (g8 >> 1);
                const uint32_t a = smb + SM_QHI + row * 128 + (((uint32_t)(c ^ (row & 7))) << 4);
                ldm_x4(qh[dc], a);
                ldm_x4(ql[dc], a + (SM_QLO - SM_QHI));
            }
        }

        float OC[8][4];
        #pragma unroll
        for (int i = 0; i < 8; i++)
            { OC[i][0] = 0.f; OC[i][1] = 0.f; OC[i][2] = 0.f; OC[i][3] = 0.f; }
        float rs0 = 0.f, rs1 = 0.f;
        const int q0 = qbase + wr * 16 + l4, q1 = q0 + 8;
        const int nkt = (qt >> 1) + 1;
        const int kb0 = wc * 64;

        #pragma unroll 1
        for (int j = 0; j < nkt; j++) {
            const int kt = j * NT;
            __syncthreads();
            stage(smb + SM_KHI, g_Khi + ((size_t)b * S_ + kt) * D_, tid, 4);
            stage(smb + SM_KLO, g_Klo + ((size_t)b * S_ + kt) * D_, tid, 4);
            stage(smb + SM_VHI, g_Vhi + ((size_t)b * S_ + kt) * D_, tid, 4);
            stage(smb + SM_VLO, g_Vlo + ((size_t)b * S_ + kt) * D_, tid, 4);
            if (tid < 128) {
                const int idx = b * S_ + kt + tid;
                float pv;
                if (kind == 0)      pv = (float)((const unsigned char*)pad)[idx];
                else if (kind == 1) pv = (float)((const int*)pad)[idx];
                else                pv = ((const float*)pad)[idx];
                padf[tid] = pv;
            }
            __syncthreads();

            // ---- S = Q K^T (3 hi/lo combos) ----
            float SC[8][4];
            #pragma unroll
            for (int i = 0; i < 8; i++)
                { SC[i][0] = 0.f; SC[i][1] = 0.f; SC[i][2] = 0.f; SC[i][3] = 0.f; }
            {
                const int krow0 = kb0 + (g8 >> 1) * 8 + l8;
                #pragma unroll
                for (int dc = 0; dc < 4; dc++) {
                    #pragma unroll
                    for (int kp = 0; kp < 4; kp++) {
                        const int row = krow0 + kp * 16;
                        const int c = 2 * dc + (g8 & 1);
                        const uint32_t a = smb + SM_KHI + row * 128 + (((uint32_t)(c ^ (row & 7))) << 4);
                        uint32_t bh[4], bl[4];
                        ldm_x4(bh, a);
                        ldm_x4(bl, a + (SM_KLO - SM_KHI));
                        mma_bf16(SC[2*kp],   qh[dc], bh);     mma_bf16(SC[2*kp],   qh[dc], bl);
                        mma_bf16(SC[2*kp],   ql[dc], bh);
                        mma_bf16(SC[2*kp+1], qh[dc], bh + 2); mma_bf16(SC[2*kp+1], qh[dc], bl + 2);
                        mma_bf16(SC[2*kp+1], ql[dc], bh + 2);
                    }
                }
            }

            // ---- mask + exp + C->A fragment conversion (hi/lo) ----
            uint32_t Ph[4][4], Pl[4][4];
            #pragma unroll
            for (int n = 0; n < 8; n++) {
                const int colb = kb0 + n * 8 + 2 * lq;
                const int key = kt + colb;
                const float pad0 = padf[colb], pad1 = padf[colb + 1];
                const float p00 = (key     <= q0 && pad0 == 0.f) ? __expf(SC[n][0] * 0.125f) : 0.f;
                const float p01 = (key + 1 <= q0 && pad1 == 0.f) ? __expf(SC[n][1] * 0.125f) : 0.f;
                const float p10 = (key     <= q1 && pad0 == 0.f) ? __expf(SC[n][2] * 0.125f) : 0.f;
                const float p11 = (key + 1 <= q1 && pad1 == 0.f) ? __expf(SC[n][3] * 0.125f) : 0.f;
                rs0 += p00 + p01;
                rs1 += p10 + p11;
                const __nv_bfloat16 h00 = __float2bfloat16_rn(p00);
                const __nv_bfloat16 h01 = __float2bfloat16_rn(p01);
                const __nv_bfloat16 h10 = __float2bfloat16_rn(p10);
                const __nv_bfloat16 h11 = __float2bfloat16_rn(p11);
                const __nv_bfloat16 l00 = __float2bfloat16_rn(p00 - __bfloat162float(h00));
                const __nv_bfloat16 l01 = __float2bfloat16_rn(p01 - __bfloat162float(h01));
                const __nv_bfloat16 l10 = __float2bfloat16_rn(p10 - __bfloat162float(h10));
                const __nv_bfloat16 l11 = __float2bfloat16_rn(p11 - __bfloat162float(h11));
                const int kc = n >> 1, sub = (n & 1) * 2;
                Ph[kc][sub]     = bfpack(h00, h01);
                Ph[kc][sub + 1] = bfpack(h10, h11);
                Pl[kc][sub]     = bfpack(l00, l01);
                Pl[kc][sub + 1] = bfpack(l10, l11);
            }

            // ---- O += P V (3 hi/lo combos; V via ldmatrix.trans) ----
            {
                const int vrow0 = kb0 + (g8 & 1) * 8 + l8;
                #pragma unroll
                for (int kc = 0; kc < 4; kc++) {
                    #pragma unroll
                    for (int ndp = 0; ndp < 4; ndp++) {
                        const int row = vrow0 + kc * 16;
                        const int c = 2 * ndp + (g8 >> 1);
                        const uint32_t a = smb + SM_VHI + row * 128 + (((uint32_t)(c ^ (row & 7))) << 4);
                        uint32_t bh[4], bl[4];
                        ldm_x4_t(bh, a);
                        ldm_x4_t(bl, a + (SM_VLO - SM_VHI));
                        mma_bf16(OC[2*ndp],   Ph[kc], bh);     mma_bf16(OC[2*ndp],   Ph[kc], bl);
                        mma_bf16(OC[2*ndp],   Pl[kc], bh);
                        mma_bf16(OC[2*ndp+1], Ph[kc], bh + 2); mma_bf16(OC[2*ndp+1], Ph[kc], bl + 2);
                        mma_bf16(OC[2*ndp+1], Pl[kc], bh + 2);
                    }
                }
            }
        }

        // ---- merge the two key-halves (ADD; no rescaling needed) ----
        rs0 += __shfl_xor_sync(0xFFFFFFFFu, rs0, 1);
        rs0 += __shfl_xor_sync(0xFFFFFFFFu, rs0, 2);
        rs1 += __shfl_xor_sync(0xFFFFFFFFu, rs1, 1);
        rs1 += __shfl_xor_sync(0xFFFFFFFFu, rs1, 2);
        if (lq == 0) {
            lsm[wc * 64 + wr * 16 + l4]     = rs0;
            lsm[wc * 64 + wr * 16 + 8 + l4] = rs1;
        }
        if (wc == 1) {
            const int r0 = wr * 16 + l4;
            #pragma unroll
            for (int nd = 0; nd < 8; nd++) {
                const int d0 = nd * 8 + 2 * lq;
                *reinterpret_cast<float2*>(&mrg[r0 * 64 + d0])       = make_float2(OC[nd][0], OC[nd][1]);
                *reinterpret_cast<float2*>(&mrg[(r0 + 8) * 64 + d0]) = make_float2(OC[nd][2], OC[nd][3]);
            }
        }
        __syncthreads();
        if (wc == 0) {
            const int r0 = wr * 16 + l4;
            const float lt0 = lsm[r0] + lsm[64 + r0];
            const float lt1 = lsm[r0 + 8] + lsm[64 + r0 + 8];
            const bool am0 = (lt0 == 0.f), am1 = (lt1 == 0.f);
            const float inv0 = am0 ? 0.f : 1.f / lt0;
            const float inv1 = am1 ? 0.f : 1.f / lt1;
            const int qr0 = qbase + r0, qr1 = qr0 + 8;
            #pragma unroll
            for (int nd = 0; nd < 8; nd++) {
                const int d0 = nd * 8 + 2 * lq;
                const float2 m0v = *reinterpret_cast<const float2*>(&mrg[r0 * 64 + d0]);
                const float2 m1v = *reinterpret_cast<const float2*>(&mrg[(r0 + 8) * 64 + d0]);
                float2 o0, o1;
                if (am0) o0 = make_float2(g_meanV[b * 64 + d0], g_meanV[b * 64 + d0 + 1]);
                else     o0 = make_float2((OC[nd][0] + m0v.x) * inv0, (OC[nd][1] + m0v.y) * inv0);
                if (am1) o1 = make_float2(g_meanV[b * 64 + d0], g_meanV[b * 64 + d0 + 1]);
                else     o1 = make_float2((OC[nd][2] + m1v.x) * inv1, (OC[nd][3] + m1v.y) * inv1);
                *reinterpret_cast<float2*>(&out[((size_t)b * S_ + qr0) * D_ + d0]) = o0;
                *reinterpret_cast<float2*>(&out[((size_t)b * S_ + qr1) * D_ + d0]) = o1;
            }
        }
    }
}

// ---------------------------------------------------------------------------
extern "C" void kernel_launch(void* const* d_in, const int* in_sizes, int n_in,
                              void* d_out, int out_size)
{
    const float* E  = (const float*)d_in[0];
    const float* PK = (const float*)d_in[1];
    const float* PV = (const float*)d_in[2];
    const float* Wq = (const float*)d_in[3];
    const float* bq = (const float*)d_in[4];
    const float* Wk = (const float*)d_in[5];
    const float* bk = (const float*)d_in[6];
    const float* Wv = (const float*)d_in[7];
    const float* bv = (const float*)d_in[8];
    const void*  pad = d_in[9];
    float* out = (float*)d_out;

    cudaFuncSetAttribute(attn_mma_kernel, cudaFuncAttributeMaxDynamicSharedMemorySize, SM_TOTAL);

    detect_pad_kernel<<<1, 1024>>>((const unsigned char*)pad);
    proj_kernel<<<B_ * S_ / 256, 256>>>(E, PK, PV, Wq, bq, Wk, bk, Wv, bv);
    meanv1_kernel<<<64, 256>>>();
    meanv2_kernel<<<1, 256>>>();
    attn_mma_kernel<<<dim3(32, B_), 256, SM_TOTAL>>>(pad, out);
}

// round 6
// speedup vs baseline: 4.4568x; 1.1095x over previous
#include <cuda_runtime.h>
#include <cuda_fp16.h>
#include <math.h>
#include <stdint.h>

// Problem constants
constexpr int B_ = 4, S_ = 4096, D_ = 64;
constexpr int MT = 64;            // q rows per tile (one phase)
constexpr int NT = 128;           // keys per k-tile
constexpr float QSCALE = 0.18033688011112042f;  // 0.125 * log2(e), folded into Q

// ---- global scratch (allocation-free rule) ----
__device__ __align__(16) __half g_Qhi[B_*S_*D_], g_Qlo[B_*S_*D_];
__device__ __align__(16) __half g_Khi[B_*S_*D_], g_Klo[B_*S_*D_];
__device__ __align__(16) __half g_Vhi[B_*S_*D_], g_Vlo[B_*S_*D_];
__device__ float g_part[64][D_];
__device__ float g_meanV[B_*D_];
__device__ int   g_padkind;       // 0=uint8, 1=int32, 2=float32

// ---- f32x2 helpers (proj kernel) ----
using u64_t = unsigned long long;
__device__ __forceinline__ u64_t fma2(u64_t a, u64_t b, u64_t c) {
    u64_t d; asm("fma.rn.f32x2 %0, %1, %2, %3;" : "=l"(d) : "l"(a), "l"(b), "l"(c)); return d;
}
__device__ __forceinline__ float2 unpack2(u64_t v) {
    float2 r; asm("mov.b64 {%0, %1}, %2;" : "=f"(r.x), "=f"(r.y) : "l"(v)); return r;
}

__device__ __forceinline__ uint32_t smem_u32(const void* p) {
    uint32_t a;
    asm("{ .reg .u64 t; cvta.to.shared.u64 t, %1; cvt.u32.u64 %0, t; }" : "=r"(a) : "l"(p));
    return a;
}

// ---- mma.sync / ldmatrix / misc PTX ----
__device__ __forceinline__ void ldm_x4(uint32_t* r, uint32_t a) {
    asm volatile("ldmatrix.sync.aligned.m8n8.x4.shared.b16 {%0,%1,%2,%3}, [%4];"
                 : "=r"(r[0]), "=r"(r[1]), "=r"(r[2]), "=r"(r[3]) : "r"(a));
}
__device__ __forceinline__ void ldm_x4_t(uint32_t* r, uint32_t a) {
    asm volatile("ldmatrix.sync.aligned.m8n8.x4.trans.shared.b16 {%0,%1,%2,%3}, [%4];"
                 : "=r"(r[0]), "=r"(r[1]), "=r"(r[2]), "=r"(r[3]) : "r"(a));
}
__device__ __forceinline__ void mma_f16(float* c, const uint32_t* a, const uint32_t* b) {
    asm volatile("mma.sync.aligned.m16n8k16.row.col.f32.f16.f16.f32 "
                 "{%0,%1,%2,%3}, {%4,%5,%6,%7}, {%8,%9}, {%0,%1,%2,%3};"
                 : "+f"(c[0]), "+f"(c[1]), "+f"(c[2]), "+f"(c[3])
                 : "r"(a[0]), "r"(a[1]), "r"(a[2]), "r"(a[3]), "r"(b[0]), "r"(b[1]));
}
__device__ __forceinline__ float ex2(float x) {
    float y; asm("ex2.approx.f32 %0, %1;" : "=f"(y) : "f"(x)); return y;
}
// pack two fp32 -> fp16x2; 'lo' lands in the LOW half
__device__ __forceinline__ uint32_t cvt_f16x2(float hi, float lo) {
    uint32_t r; asm("cvt.rn.f16x2.f32 %0, %1, %2;" : "=r"(r) : "f"(hi), "f"(lo)); return r;
}
__device__ __forceinline__ void cpa16(uint32_t dst, const void* src) {
    asm volatile("cp.async.cg.shared.global [%0], [%1], 16;" :: "r"(dst), "l"(src));
}
#define CP_COMMIT() asm volatile("cp.async.commit_group;" ::: "memory")
#define CP_WAIT0()  asm volatile("cp.async.wait_group 0;" ::: "memory")

// ---------------------------------------------------------------------------
// Kernel 0: detect pad_mask storage dtype (reads first 16384 bytes only).
// ---------------------------------------------------------------------------
__global__ void detect_pad_kernel(const unsigned char* __restrict__ p)
{
    __shared__ int f[2];
    const int t = threadIdx.x;
    if (t < 2) f[t] = 0;
    __syncthreads();
    int ge2 = 0, odd = 0;
    for (int i = t; i < B_ * S_; i += blockDim.x) {
        unsigned v = p[i];
        if (v >= 2u) ge2 = 1;
        if ((i & 3) && v) odd = 1;
    }
    if (ge2) atomicOr(&f[0], 1);
    if (odd) atomicOr(&f[1], 1);
    __syncthreads();
    if (t == 0) g_padkind = f[0] ? 2 : (f[1] ? 0 : 1);
}

// ---------------------------------------------------------------------------
// Kernel 1: fused QKV projection + popularity modulation + fp16 hi/lo split.
// Q is prescaled by 0.125*log2(e) so attention uses ex2 directly.
// ---------------------------------------------------------------------------
__global__ __launch_bounds__(256) void proj_kernel(
    const float* __restrict__ E,  const float* __restrict__ PK, const float* __restrict__ PV,
    const float* __restrict__ Wq, const float* __restrict__ bq,
    const float* __restrict__ Wk, const float* __restrict__ bk,
    const float* __restrict__ Wv, const float* __restrict__ bv)
{
    __shared__ float Wsm[3][D_ * D_];
    const int t = threadIdx.x;
    const size_t g = (size_t)blockIdx.x * 256 + t;

    {
        const float* Ws[3] = {Wq, Wk, Wv};
        #pragma unroll
        for (int m = 0; m < 3; m++) {
            float4* dst = reinterpret_cast<float4*>(Wsm[m]);
            const float4* src = reinterpret_cast<const float4*>(Ws[m]);
            #pragma unroll
            for (int i = 0; i < 4; i++) dst[t + i * 256] = src[t + i * 256];
        }
    }
    __syncthreads();

    u64_t e2[32];
    {
        const ulonglong2* er = reinterpret_cast<const ulonglong2*>(E + g * D_);
        #pragma unroll
        for (int i = 0; i < 16; i++) { ulonglong2 v = er[i]; e2[2*i] = v.x; e2[2*i+1] = v.y; }
    }

    const float* bsx[3] = {bq, bk, bv};
    __half* ohi[3] = {g_Qhi, g_Khi, g_Vhi};
    __half* olo[3] = {g_Qlo, g_Klo, g_Vlo};

    #pragma unroll
    for (int m = 0; m < 3; m++) {
        float outv[D_];
        for (int c = 0; c < D_; c++) {
            const ulonglong2* wr = reinterpret_cast<const ulonglong2*>(Wsm[m] + c * D_);
            u64_t a0 = 0ull, a1 = 0ull;
            #pragma unroll
            for (int d8 = 0; d8 < 16; d8++) {
                ulonglong2 w = wr[d8];
                a0 = fma2(e2[2*d8],   w.x, a0);
                a1 = fma2(e2[2*d8+1], w.y, a1);
            }
            float2 p0 = unpack2(a0), p1 = unpack2(a1);
            outv[c] = bsx[m][c] + ((p0.x + p0.y) + (p1.x + p1.y));
        }
        if (m == 0) {
            #pragma unroll
            for (int c = 0; c < D_; c++) outv[c] *= QSCALE;
        } else {
            const float* mod = (m == 1 ? PK : PV) + g * D_;
            #pragma unroll
            for (int c = 0; c < D_; c++) outv[c] *= mod[c];
        }
        unsigned short hib[D_], lob[D_];
        #pragma unroll
        for (int c = 0; c < D_; c++) {
            __half h = __float2half_rn(outv[c]);
            float rest = outv[c] - __half2float(h);
            __half l = __float2half_rn(rest);
            hib[c] = __half_as_ushort(h);
            lob[c] = __half_as_ushort(l);
        }
        uint4* oh = reinterpret_cast<uint4*>(ohi[m] + g * D_);
        uint4* ol = reinterpret_cast<uint4*>(olo[m] + g * D_);
        const uint4* sh = reinterpret_cast<const uint4*>(hib);
        const uint4* sl = reinterpret_cast<const uint4*>(lob);
        #pragma unroll
        for (int i = 0; i < 8; i++) { oh[i] = sh[i]; ol[i] = sl[i]; }
    }
}

// ---------------------------------------------------------------------------
// Kernel 2a/2b: per-batch mean of V_p (fallback for fully-masked rows)
// ---------------------------------------------------------------------------
__global__ __launch_bounds__(256) void meanv1_kernel()
{
    const int blk = blockIdx.x;
    const int t = threadIdx.x;
    const int d = t & 63;
    const int part = t >> 6;
    float acc = 0.f;
    const __half* bh = g_Vhi + ((size_t)blk * 256 + part * 64) * D_ + d;
    const __half* bl = g_Vlo + ((size_t)blk * 256 + part * 64) * D_ + d;
    for (int i = 0; i < 64; i++)
        acc += __half2float(bh[(size_t)i * D_]) + __half2float(bl[(size_t)i * D_]);
    __shared__ float red[256];
    red[t] = acc;
    __syncthreads();
    if (t < 64)
        g_part[blk][t] = red[t] + red[t + 64] + red[t + 128] + red[t + 192];
}

__global__ void meanv2_kernel()
{
    const int t = threadIdx.x;
    const int b = t >> 6, d = t & 63;
    float a = 0.f;
    #pragma unroll
    for (int i = 0; i < 16; i++) a += g_part[b * 16 + i][d];
    g_meanV[b * 64 + d] = a * (1.0f / (float)S_);
}

// ---------------------------------------------------------------------------
// Kernel 3: mma.sync fp16 hi/lo flash attention, cp.async double-buffered.
// CTA = 256 threads = 4 row-warps x 2 key-halves over a 64-row q-tile.
// Pair scheduling (qt, 63-qt): exactly 33 k-tiles per CTA.
// ---------------------------------------------------------------------------
constexpr int SM_QHI  = 0;                      // 64 x 128B
constexpr int SM_QLO  = 8192;
constexpr int SM_KV   = 16384;                  // 2 stages x 4 tiles x 16KB
constexpr int STG_SZ  = 65536;
constexpr int OFF_KHI = 0, OFF_KLO = 16384, OFF_VHI = 32768, OFF_VLO = 49152;
constexpr int SM_PADB = SM_KV + 2 * STG_SZ;     // 147456, 2 x 512B
constexpr int SM_LSM  = SM_PADB + 1024;         // 148480, 2 x 64 f32
constexpr int SM_MRG  = SM_KV;                  // merge overlays stage 0 (pipeline drained)
constexpr int SM_TOTAL = SM_LSM + 512;          // 148992

__global__ __launch_bounds__(256, 1) void attn_mma_kernel(const void* __restrict__ pad,
                                                          float* __restrict__ out)
{
    extern __shared__ char sm[];
    const uint32_t smb = smem_u32(sm);
    const int tid = threadIdx.x, wid = tid >> 5, lane = tid & 31;
    const int wr = wid & 3, wc = wid >> 2;        // row-warp, key-half
    const int b = blockIdx.y, kind = g_padkind;
    const int g8 = lane >> 3, l8 = lane & 7, l4 = lane >> 2, lq = lane & 3;
    float* lsm  = reinterpret_cast<float*>(sm + SM_LSM);
    float* mrg  = reinterpret_cast<float*>(sm + SM_MRG);
    const int esz = (kind == 0) ? 1 : 4;
    const int npadch = (128 * esz) >> 4;          // 8 or 32 16B chunks

    #pragma unroll 1
    for (int phase = 0; phase < 2; phase++) {
        const int qt = phase ? (63 - blockIdx.x) : blockIdx.x;
        const int qbase = qt * MT;
        const int nkt = (qt >> 1) + 1;

        __syncthreads();   // prev phase merge reads done; smem reusable

        // ---- prologue: async-copy Q (hi/lo) + k-tile 0 into stage 0 ----
        {
            const uint4* qh = reinterpret_cast<const uint4*>(g_Qhi + ((size_t)b * S_ + qbase) * D_);
            const uint4* ql = reinterpret_cast<const uint4*>(g_Qlo + ((size_t)b * S_ + qbase) * D_);
            #pragma unroll
            for (int it = 0; it < 2; it++) {
                int i = tid + it * 256;            // 512 chunks each
                int row = i >> 3, c = i & 7;
                uint32_t sw = row * 128 + (((uint32_t)(c ^ (row & 7))) << 4);
                cpa16(smb + SM_QHI + sw, qh + i);
                cpa16(smb + SM_QLO + sw, ql + i);
            }
            const __half* srcs[4] = {g_Khi + (size_t)b * S_ * D_, g_Klo + (size_t)b * S_ * D_,
                                     g_Vhi + (size_t)b * S_ * D_, g_Vlo + (size_t)b * S_ * D_};
            #pragma unroll
            for (int t4 = 0; t4 < 4; t4++) {
                #pragma unroll
                for (int it = 0; it < 4; it++) {
                    int i = tid + it * 256;        // 1024 chunks per tile
                    int row = i >> 3, c = i & 7;
                    uint32_t dst = smb + SM_KV + t4 * 16384 + row * 128 + (((uint32_t)(c ^ (row & 7))) << 4);
                    cpa16(dst, reinterpret_cast<const uint4*>(srcs[t4]) + i);
                }
            }
            if (tid < npadch)
                cpa16(smb + SM_PADB + tid * 16,
                      (const char*)pad + (size_t)(b * S_) * esz + tid * 16);
            CP_COMMIT();
        }
        CP_WAIT0();
        __syncthreads();

        // ---- Q A-fragments (hi/lo), 4 d-chunks of 16 ----
        uint32_t qh[4][4], ql[4][4];
        {
            const int row = wr * 16 + (g8 & 1) * 8 + l8;
            #pragma unroll
            for (int dc = 0; dc < 4; dc++) {
                const int c = 2 * dc + (g8 >> 1);
                const uint32_t a = smb + SM_QHI + row * 128 + (((uint32_t)(c ^ (row & 7))) << 4);
                ldm_x4(qh[dc], a);
                ldm_x4(ql[dc], a + (SM_QLO - SM_QHI));
            }
        }

        float OC[8][4];
        #pragma unroll
        for (int i = 0; i < 8; i++)
            { OC[i][0] = 0.f; OC[i][1] = 0.f; OC[i][2] = 0.f; OC[i][3] = 0.f; }
        float rs0 = 0.f, rs1 = 0.f;
        const int q0 = qbase + wr * 16 + l4, q1 = q0 + 8;
        const int kb0 = wc * 64;

        #pragma unroll 1
        for (int j = 0; j < nkt; j++) {
            const int st = j & 1;
            const uint32_t stb = smb + SM_KV + st * STG_SZ;
            const char* padsm = sm + SM_PADB + st * 512;
            const int kt = j * NT;

            // issue copy for tile j+1 into the other stage (overlaps compute)
            if (j + 1 < nkt) {
                const int ktn = (j + 1) * NT;
                const uint32_t nstb = smb + SM_KV + ((j + 1) & 1) * STG_SZ;
                const __half* srcs[4] = {g_Khi + ((size_t)b * S_ + ktn) * D_,
                                         g_Klo + ((size_t)b * S_ + ktn) * D_,
                                         g_Vhi + ((size_t)b * S_ + ktn) * D_,
                                         g_Vlo + ((size_t)b * S_ + ktn) * D_};
                #pragma unroll
                for (int t4 = 0; t4 < 4; t4++) {
                    #pragma unroll
                    for (int it = 0; it < 4; it++) {
                        int i = tid + it * 256;
                        int row = i >> 3, c = i & 7;
                        uint32_t dst = nstb + t4 * 16384 + row * 128 + (((uint32_t)(c ^ (row & 7))) << 4);
                        cpa16(dst, reinterpret_cast<const uint4*>(srcs[t4]) + i);
                    }
                }
                if (tid < npadch)
                    cpa16(smb + SM_PADB + ((j + 1) & 1) * 512 + tid * 16,
                          (const char*)pad + (size_t)(b * S_ + ktn) * esz + tid * 16);
                CP_COMMIT();
            }

            // ---- S = Q K^T (3 hi/lo combos) ----
            float SC[8][4];
            #pragma unroll
            for (int i = 0; i < 8; i++)
                { SC[i][0] = 0.f; SC[i][1] = 0.f; SC[i][2] = 0.f; SC[i][3] = 0.f; }
            {
                const int krow0 = kb0 + (g8 >> 1) * 8 + l8;
                #pragma unroll
                for (int dc = 0; dc < 4; dc++) {
                    #pragma unroll
                    for (int kp = 0; kp < 4; kp++) {
                        const int row = krow0 + kp * 16;
                        const int c = 2 * dc + (g8 & 1);
                        const uint32_t a = stb + OFF_KHI + row * 128 + (((uint32_t)(c ^ (row & 7))) << 4);
                        uint32_t bh[4], bl[4];
                        ldm_x4(bh, a);
                        ldm_x4(bl, a + (OFF_KLO - OFF_KHI));
                        mma_f16(SC[2*kp],   qh[dc], bh);     mma_f16(SC[2*kp],   qh[dc], bl);
                        mma_f16(SC[2*kp],   ql[dc], bh);
                        mma_f16(SC[2*kp+1], qh[dc], bh + 2); mma_f16(SC[2*kp+1], qh[dc], bl + 2);
                        mma_f16(SC[2*kp+1], ql[dc], bh + 2);
                    }
                }
            }

            // ---- mask + ex2 + C->A fragment conversion (fp16 hi/lo) ----
            uint32_t Ph[4][4], Pl[4][4];
            #pragma unroll
            for (int n = 0; n < 8; n++) {
                const int colb = kb0 + n * 8 + 2 * lq;
                const int key = kt + colb;
                float pad0, pad1;
                if (kind == 0) {
                    pad0 = (float)((const unsigned char*)padsm)[colb];
                    pad1 = (float)((const unsigned char*)padsm)[colb + 1];
                } else if (kind == 1) {
                    pad0 = (float)((const int*)padsm)[colb];
                    pad1 = (float)((const int*)padsm)[colb + 1];
                } else {
                    pad0 = ((const float*)padsm)[colb];
                    pad1 = ((const float*)padsm)[colb + 1];
                }
                const float p00 = (key     <= q0 && pad0 == 0.f) ? ex2(SC[n][0]) : 0.f;
                const float p01 = (key + 1 <= q0 && pad1 == 0.f) ? ex2(SC[n][1]) : 0.f;
                const float p10 = (key     <= q1 && pad0 == 0.f) ? ex2(SC[n][2]) : 0.f;
                const float p11 = (key + 1 <= q1 && pad1 == 0.f) ? ex2(SC[n][3]) : 0.f;
                rs0 += p00 + p01;
                rs1 += p10 + p11;
                const uint32_t hA = cvt_f16x2(p01, p00);
                const uint32_t hB = cvt_f16x2(p11, p10);
                const half2 hA2 = *reinterpret_cast<const half2*>(&hA);
                const half2 hB2 = *reinterpret_cast<const half2*>(&hB);
                const float2 fA = __half22float2(hA2);
                const float2 fB = __half22float2(hB2);
                const uint32_t lA = cvt_f16x2(p01 - fA.y, p00 - fA.x);
                const uint32_t lB = cvt_f16x2(p11 - fB.y, p10 - fB.x);
                const int kc = n >> 1, sub = (n & 1) * 2;
                Ph[kc][sub] = hA; Ph[kc][sub + 1] = hB;
                Pl[kc][sub] = lA; Pl[kc][sub + 1] = lB;
            }

            // ---- O += P V (3 hi/lo combos; V via ldmatrix.trans) ----
            {
                const int vrow0 = kb0 + (g8 & 1) * 8 + l8;
                #pragma unroll
                for (int kc = 0; kc < 4; kc++) {
                    #pragma unroll
                    for (int ndp = 0; ndp < 4; ndp++) {
                        const int row = vrow0 + kc * 16;
                        const int c = 2 * ndp + (g8 >> 1);
                        const uint32_t a = stb + OFF_VHI + row * 128 + (((uint32_t)(c ^ (row & 7))) << 4);
                        uint32_t bh[4], bl[4];
                        ldm_x4_t(bh, a);
                        ldm_x4_t(bl, a + (OFF_VLO - OFF_VHI));
                        mma_f16(OC[2*ndp],   Ph[kc], bh);     mma_f16(OC[2*ndp],   Ph[kc], bl);
                        mma_f16(OC[2*ndp],   Pl[kc], bh);
                        mma_f16(OC[2*ndp+1], Ph[kc], bh + 2); mma_f16(OC[2*ndp+1], Ph[kc], bl + 2);
                        mma_f16(OC[2*ndp+1], Pl[kc], bh + 2);
                    }
                }
            }

            if (j + 1 < nkt) CP_WAIT0();
            __syncthreads();
        }

        // ---- merge the two key-halves (ADD; no rescaling needed) ----
        rs0 += __shfl_xor_sync(0xFFFFFFFFu, rs0, 1);
        rs0 += __shfl_xor_sync(0xFFFFFFFFu, rs0, 2);
        rs1 += __shfl_xor_sync(0xFFFFFFFFu, rs1, 1);
        rs1 += __shfl_xor_sync(0xFFFFFFFFu, rs1, 2);
        if (lq == 0) {
            lsm[wc * 64 + wr * 16 + l4]     = rs0;
            lsm[wc * 64 + wr * 16 + 8 + l4] = rs1;
        }
        if (wc == 1) {
            const int r0 = wr * 16 + l4;
            #pragma unroll
            for (int nd = 0; nd < 8; nd++) {
                const int d0 = nd * 8 + 2 * lq;
                *reinterpret_cast<float2*>(&mrg[r0 * 64 + d0])       = make_float2(OC[nd][0], OC[nd][1]);
                *reinterpret_cast<float2*>(&mrg[(r0 + 8) * 64 + d0]) = make_float2(OC[nd][2], OC[nd][3]);
            }
        }
        __syncthreads();
        if (wc == 0) {
            const int r0 = wr * 16 + l4;
            const float lt0 = lsm[r0] + lsm[64 + r0];
            const float lt1 = lsm[r0 + 8] + lsm[64 + r0 + 8];
            const bool am0 = (lt0 == 0.f), am1 = (lt1 == 0.f);
            const float inv0 = am0 ? 0.f : 1.f / lt0;
            const float inv1 = am1 ? 0.f : 1.f / lt1;
            const int qr0 = qbase + r0, qr1 = qr0 + 8;
            #pragma unroll
            for (int nd = 0; nd < 8; nd++) {
                const int d0 = nd * 8 + 2 * lq;
                const float2 m0v = *reinterpret_cast<const float2*>(&mrg[r0 * 64 + d0]);
                const float2 m1v = *reinterpret_cast<const float2*>(&mrg[(r0 + 8) * 64 + d0]);
                float2 o0, o1;
                if (am0) o0 = make_float2(g_meanV[b * 64 + d0], g_meanV[b * 64 + d0 + 1]);
                else     o0 = make_float2((OC[nd][0] + m0v.x) * inv0, (OC[nd][1] + m0v.y) * inv0);
                if (am1) o1 = make_float2(g_meanV[b * 64 + d0], g_meanV[b * 64 + d0 + 1]);
                else     o1 = make_float2((OC[nd][2] + m1v.x) * inv1, (OC[nd][3] + m1v.y) * inv1);
                *reinterpret_cast<float2*>(&out[((size_t)b * S_ + qr0) * D_ + d0]) = o0;
                *reinterpret_cast<float2*>(&out[((size_t)b * S_ + qr1) * D_ + d0]) = o1;
            }
        }
    }
}

// ---------------------------------------------------------------------------
extern "C" void kernel_launch(void* const* d_in, const int* in_sizes, int n_in,
                              void* d_out, int out_size)
{
    const float* E  = (const float*)d_in[0];
    const float* PK = (const float*)d_in[1];
    const float* PV = (const float*)d_in[2];
    const float* Wq = (const float*)d_in[3];
    const float* bq = (const float*)d_in[4];
    const float* Wk = (const float*)d_in[5];
    const float* bk = (const float*)d_in[6];
    const float* Wv = (const float*)d_in[7];
    const float* bv = (const float*)d_in[8];
    const void*  pad = d_in[9];
    float* out = (float*)d_out;

    cudaFuncSetAttribute(attn_mma_kernel, cudaFuncAttributeMaxDynamicSharedMemorySize, SM_TOTAL);

    detect_pad_kernel<<<1, 1024>>>((const unsigned char*)pad);
    proj_kernel<<<B_ * S_ / 256, 256>>>(E, PK, PV, Wq, bq, Wk, bk, Wv, bv);
    meanv1_kernel<<<64, 256>>>();
    meanv2_kernel<<<1, 256>>>();
    attn_mma_kernel<<<dim3(32, B_), 256, SM_TOTAL>>>(pad, out);
}

// round 7
// speedup vs baseline: 7.3897x; 1.6581x over previous
#include <cuda_runtime.h>
#include <cuda_fp16.h>
#include <math.h>
#include <stdint.h>

// Problem constants
constexpr int B_ = 4, S_ = 4096, D_ = 64;
constexpr int MT = 64;            // q rows per tile (one phase)
constexpr int NT = 128;           // keys per k-tile
constexpr float QSCALE = 0.18033688011112042f;  // 0.125 * log2(e), folded into Q

// ---- global scratch (allocation-free rule) ----
__device__ __align__(16) __half g_Qh[B_*S_*D_];
__device__ __align__(16) __half g_Kh[B_*S_*D_];
__device__ __align__(16) __half g_Vh[B_*S_*D_];
__device__ float g_part[64][D_];
__device__ float g_meanV[B_*D_];
__device__ int   g_padkind;       // 0=uint8, 1=int32, 2=float32

// ---- f32x2 helpers (proj kernel) ----
using u64_t = unsigned long long;
__device__ __forceinline__ u64_t fma2(u64_t a, u64_t b, u64_t c) {
    u64_t d; asm("fma.rn.f32x2 %0, %1, %2, %3;" : "=l"(d) : "l"(a), "l"(b), "l"(c)); return d;
}
__device__ __forceinline__ float2 unpack2(u64_t v) {
    float2 r; asm("mov.b64 {%0, %1}, %2;" : "=f"(r.x), "=f"(r.y) : "l"(v)); return r;
}

__device__ __forceinline__ uint32_t smem_u32(const void* p) {
    uint32_t a;
    asm("{ .reg .u64 t; cvta.to.shared.u64 t, %1; cvt.u32.u64 %0, t; }" : "=r"(a) : "l"(p));
    return a;
}

// ---- mma.sync / ldmatrix / misc PTX ----
__device__ __forceinline__ void ldm_x4(uint32_t* r, uint32_t a) {
    asm volatile("ldmatrix.sync.aligned.m8n8.x4.shared.b16 {%0,%1,%2,%3}, [%4];"
                 : "=r"(r[0]), "=r"(r[1]), "=r"(r[2]), "=r"(r[3]) : "r"(a));
}
__device__ __forceinline__ void ldm_x4_t(uint32_t* r, uint32_t a) {
    asm volatile("ldmatrix.sync.aligned.m8n8.x4.trans.shared.b16 {%0,%1,%2,%3}, [%4];"
                 : "=r"(r[0]), "=r"(r[1]), "=r"(r[2]), "=r"(r[3]) : "r"(a));
}
__device__ __forceinline__ void mma_f16(float* c, const uint32_t* a, const uint32_t* b) {
    asm volatile("mma.sync.aligned.m16n8k16.row.col.f32.f16.f16.f32 "
                 "{%0,%1,%2,%3}, {%4,%5,%6,%7}, {%8,%9}, {%0,%1,%2,%3};"
                 : "+f"(c[0]), "+f"(c[1]), "+f"(c[2]), "+f"(c[3])
                 : "r"(a[0]), "r"(a[1]), "r"(a[2]), "r"(a[3]), "r"(b[0]), "r"(b[1]));
}
__device__ __forceinline__ float ex2(float x) {
    float y; asm("ex2.approx.f32 %0, %1;" : "=f"(y) : "f"(x)); return y;
}
// pack two fp32 -> fp16x2; second arg lands in the LOW half
__device__ __forceinline__ uint32_t cvt_f16x2(float hi, float lo) {
    uint32_t r; asm("cvt.rn.f16x2.f32 %0, %1, %2;" : "=r"(r) : "f"(hi), "f"(lo)); return r;
}
__device__ __forceinline__ void cpa16(uint32_t dst, const void* src) {
    asm volatile("cp.async.cg.shared.global [%0], [%1], 16;" :: "r"(dst), "l"(src));
}
#define CP_COMMIT() asm volatile("cp.async.commit_group;" ::: "memory")
#define CP_WAIT0()  asm volatile("cp.async.wait_group 0;" ::: "memory")

// ---------------------------------------------------------------------------
// Kernel 0: detect pad_mask storage dtype (reads first 16384 bytes only).
// ---------------------------------------------------------------------------
__global__ void detect_pad_kernel(const unsigned char* __restrict__ p)
{
    __shared__ int f[2];
    const int t = threadIdx.x;
    if (t < 2) f[t] = 0;
    __syncthreads();
    int ge2 = 0, odd = 0;
    for (int i = t; i < B_ * S_; i += blockDim.x) {
        unsigned v = p[i];
        if (v >= 2u) ge2 = 1;
        if ((i & 3) && v) odd = 1;
    }
    if (ge2) atomicOr(&f[0], 1);
    if (odd) atomicOr(&f[1], 1);
    __syncthreads();
    if (t == 0) g_padkind = f[0] ? 2 : (f[1] ? 0 : 1);
}

// ---------------------------------------------------------------------------
// Kernel 1: fused QKV projection + popularity modulation -> single fp16.
// Q prescaled by 0.125*log2(e). 128 blocks x 128 threads (one row/thread).
// ---------------------------------------------------------------------------
__global__ __launch_bounds__(128) void proj_kernel(
    const float* __restrict__ E,  const float* __restrict__ PK, const float* __restrict__ PV,
    const float* __restrict__ Wq, const float* __restrict__ bq,
    const float* __restrict__ Wk, const float* __restrict__ bk,
    const float* __restrict__ Wv, const float* __restrict__ bv)
{
    __shared__ float Wsm[3][D_ * D_];
    const int t = threadIdx.x;
    const size_t g = (size_t)blockIdx.x * 128 + t;

    {
        const float* Ws[3] = {Wq, Wk, Wv};
        #pragma unroll
        for (int m = 0; m < 3; m++) {
            float4* dst = reinterpret_cast<float4*>(Wsm[m]);
            const float4* src = reinterpret_cast<const float4*>(Ws[m]);
            #pragma unroll
            for (int i = 0; i < 8; i++) dst[t + i * 128] = src[t + i * 128];
        }
    }
    __syncthreads();

    u64_t e2[32];
    {
        const ulonglong2* er = reinterpret_cast<const ulonglong2*>(E + g * D_);
        #pragma unroll
        for (int i = 0; i < 16; i++) { ulonglong2 v = er[i]; e2[2*i] = v.x; e2[2*i+1] = v.y; }
    }

    const float* bsx[3] = {bq, bk, bv};
    __half* oh3[3] = {g_Qh, g_Kh, g_Vh};

    #pragma unroll
    for (int m = 0; m < 3; m++) {
        float outv[D_];
        for (int c = 0; c < D_; c++) {
            const ulonglong2* wr = reinterpret_cast<const ulonglong2*>(Wsm[m] + c * D_);
            u64_t a0 = 0ull, a1 = 0ull;
            #pragma unroll
            for (int d8 = 0; d8 < 16; d8++) {
                ulonglong2 w = wr[d8];
                a0 = fma2(e2[2*d8],   w.x, a0);
                a1 = fma2(e2[2*d8+1], w.y, a1);
            }
            float2 p0 = unpack2(a0), p1 = unpack2(a1);
            outv[c] = bsx[m][c] + ((p0.x + p0.y) + (p1.x + p1.y));
        }
        if (m == 0) {
            #pragma unroll
            for (int c = 0; c < D_; c++) outv[c] *= QSCALE;
        } else {
            const float* mod = (m == 1 ? PK : PV) + g * D_;
            #pragma unroll
            for (int c = 0; c < D_; c++) outv[c] *= mod[c];
        }
        unsigned short hb[D_];
        #pragma unroll
        for (int c = 0; c < D_; c++)
            hb[c] = __half_as_ushort(__float2half_rn(outv[c]));
        uint4* oh = reinterpret_cast<uint4*>(oh3[m] + g * D_);
        const uint4* sh = reinterpret_cast<const uint4*>(hb);
        #pragma unroll
        for (int i = 0; i < 8; i++) oh[i] = sh[i];
    }
}

// ---------------------------------------------------------------------------
// Kernel 2a/2b: per-batch mean of V_p (fallback for fully-masked rows)
// ---------------------------------------------------------------------------
__global__ __launch_bounds__(256) void meanv1_kernel()
{
    const int blk = blockIdx.x;
    const int t = threadIdx.x;
    const int d = t & 63;
    const int part = t >> 6;
    float acc = 0.f;
    const __half* bh = g_Vh + ((size_t)blk * 256 + part * 64) * D_ + d;
    for (int i = 0; i < 64; i++)
        acc += __half2float(bh[(size_t)i * D_]);
    __shared__ float red[256];
    red[t] = acc;
    __syncthreads();
    if (t < 64)
        g_part[blk][t] = red[t] + red[t + 64] + red[t + 128] + red[t + 192];
}

__global__ void meanv2_kernel()
{
    const int t = threadIdx.x;
    const int b = t >> 6, d = t & 63;
    float a = 0.f;
    #pragma unroll
    for (int i = 0; i < 16; i++) a += g_part[b * 16 + i][d];
    g_meanV[b * 64 + d] = a * (1.0f / (float)S_);
}

// ---------------------------------------------------------------------------
// Kernel 3: single-fp16 mma.sync flash attention, cp.async double-buffered.
// CTA = 256 threads = 4 row-warps x 2 key-halves over a 64-row q-tile.
// Pair scheduling (qt, 63-qt): exactly 33 k-tiles per CTA.
// l accumulates the SAME fp16-rounded p used in the PV GEMM, so P-rounding
// error largely cancels in the final normalization.
// ---------------------------------------------------------------------------
constexpr int SM_QH   = 0;                      // 64 x 128B
constexpr int SM_KV   = 8192;                   // 2 stages x (K 16KB + V 16KB)
constexpr int STG_SZ  = 32768;
constexpr int OFF_K   = 0, OFF_V = 16384;
constexpr int SM_PADB = SM_KV + 2 * STG_SZ;     // 73728, 2 x 512B
constexpr int SM_LSM  = SM_PADB + 1024;         // 74752, 2 x 64 f32
constexpr int SM_MRG  = SM_KV;                  // merge overlays stage 0 (drained)
constexpr int SM_TOTAL = SM_LSM + 512;          // 75264

__global__ __launch_bounds__(256, 1) void attn_mma_kernel(const void* __restrict__ pad,
                                                          float* __restrict__ out)
{
    extern __shared__ char sm[];
    const uint32_t smb = smem_u32(sm);
    const int tid = threadIdx.x, wid = tid >> 5, lane = tid & 31;
    const int wr = wid & 3, wc = wid >> 2;        // row-warp, key-half
    const int b = blockIdx.y, kind = g_padkind;
    const int g8 = lane >> 3, l8 = lane & 7, l4 = lane >> 2, lq = lane & 3;
    float* lsm  = reinterpret_cast<float*>(sm + SM_LSM);
    float* mrg  = reinterpret_cast<float*>(sm + SM_MRG);
    const int esz = (kind == 0) ? 1 : 4;
    const int npadch = (128 * esz) >> 4;          // 8 or 32 16B chunks

    #pragma unroll 1
    for (int phase = 0; phase < 2; phase++) {
        const int qt = phase ? (63 - blockIdx.x) : blockIdx.x;
        const int qbase = qt * MT;
        const int nkt = (qt >> 1) + 1;

        __syncthreads();   // prev phase merge reads done; smem reusable

        // ---- prologue: async-copy Q + k-tile 0 into stage 0 ----
        {
            const uint4* qh4 = reinterpret_cast<const uint4*>(g_Qh + ((size_t)b * S_ + qbase) * D_);
            #pragma unroll
            for (int it = 0; it < 2; it++) {
                int i = tid + it * 256;            // 512 chunks
                int row = i >> 3, c = i & 7;
                uint32_t sw = row * 128 + (((uint32_t)(c ^ (row & 7))) << 4);
                cpa16(smb + SM_QH + sw, qh4 + i);
            }
            const __half* srcs[2] = {g_Kh + (size_t)b * S_ * D_, g_Vh + (size_t)b * S_ * D_};
            #pragma unroll
            for (int t2 = 0; t2 < 2; t2++) {
                #pragma unroll
                for (int it = 0; it < 4; it++) {
                    int i = tid + it * 256;        // 1024 chunks per tile
                    int row = i >> 3, c = i & 7;
                    uint32_t dst = smb + SM_KV + t2 * 16384 + row * 128 + (((uint32_t)(c ^ (row & 7))) << 4);
                    cpa16(dst, reinterpret_cast<const uint4*>(srcs[t2]) + i);
                }
            }
            if (tid < npadch)
                cpa16(smb + SM_PADB + tid * 16,
                      (const char*)pad + (size_t)(b * S_) * esz + tid * 16);
            CP_COMMIT();
        }
        CP_WAIT0();
        __syncthreads();

        // ---- Q A-fragments, 4 d-chunks of 16 ----
        uint32_t qh[4][4];
        {
            const int row = wr * 16 + (g8 & 1) * 8 + l8;
            #pragma unroll
            for (int dc = 0; dc < 4; dc++) {
                const int c = 2 * dc + (g8 >> 1);
                ldm_x4(qh[dc], smb + SM_QH + row * 128 + (((uint32_t)(c ^ (row & 7))) << 4));
            }
        }

        float OC[8][4];
        #pragma unroll
        for (int i = 0; i < 8; i++)
            { OC[i][0] = 0.f; OC[i][1] = 0.f; OC[i][2] = 0.f; OC[i][3] = 0.f; }
        float rs0 = 0.f, rs1 = 0.f;
        const int q0 = qbase + wr * 16 + l4, q1 = q0 + 8;
        const int kb0 = wc * 64;

        #pragma unroll 1
        for (int j = 0; j < nkt; j++) {
            const int st = j & 1;
            const uint32_t stb = smb + SM_KV + st * STG_SZ;
            const char* padsm = sm + SM_PADB + st * 512;
            const int kt = j * NT;

            // issue copy for tile j+1 into the other stage (overlaps compute)
            if (j + 1 < nkt) {
                const int ktn = (j + 1) * NT;
                const uint32_t nstb = smb + SM_KV + ((j + 1) & 1) * STG_SZ;
                const __half* srcs[2] = {g_Kh + ((size_t)b * S_ + ktn) * D_,
                                         g_Vh + ((size_t)b * S_ + ktn) * D_};
                #pragma unroll
                for (int t2 = 0; t2 < 2; t2++) {
                    #pragma unroll
                    for (int it = 0; it < 4; it++) {
                        int i = tid + it * 256;
                        int row = i >> 3, c = i & 7;
                        uint32_t dst = nstb + t2 * 16384 + row * 128 + (((uint32_t)(c ^ (row & 7))) << 4);
                        cpa16(dst, reinterpret_cast<const uint4*>(srcs[t2]) + i);
                    }
                }
                if (tid < npadch)
                    cpa16(smb + SM_PADB + ((j + 1) & 1) * 512 + tid * 16,
                          (const char*)pad + (size_t)(b * S_ + ktn) * esz + tid * 16);
                CP_COMMIT();
            }

            // ---- S = Q K^T (single fp16) ----
            float SC[8][4];
            #pragma unroll
            for (int i = 0; i < 8; i++)
                { SC[i][0] = 0.f; SC[i][1] = 0.f; SC[i][2] = 0.f; SC[i][3] = 0.f; }
            {
                const int krow0 = kb0 + (g8 >> 1) * 8 + l8;
                #pragma unroll
                for (int dc = 0; dc < 4; dc++) {
                    #pragma unroll
                    for (int kp = 0; kp < 4; kp++) {
                        const int row = krow0 + kp * 16;
                        const int c = 2 * dc + (g8 & 1);
                        uint32_t bh[4];
                        ldm_x4(bh, stb + OFF_K + row * 128 + (((uint32_t)(c ^ (row & 7))) << 4));
                        mma_f16(SC[2*kp],   qh[dc], bh);
                        mma_f16(SC[2*kp+1], qh[dc], bh + 2);
                    }
                }
            }

            // ---- mask + ex2 + C->A fragment conversion ----
            uint32_t Ph[4][4];
            #pragma unroll
            for (int n = 0; n < 8; n++) {
                const int colb = kb0 + n * 8 + 2 * lq;
                const int key = kt + colb;
                float pad0, pad1;
                if (kind == 0) {
                    pad0 = (float)((const unsigned char*)padsm)[colb];
                    pad1 = (float)((const unsigned char*)padsm)[colb + 1];
                } else if (kind == 1) {
                    pad0 = (float)((const int*)padsm)[colb];
                    pad1 = (float)((const int*)padsm)[colb + 1];
                } else {
                    pad0 = ((const float*)padsm)[colb];
                    pad1 = ((const float*)padsm)[colb + 1];
                }
                const float p00 = (key     <= q0 && pad0 == 0.f) ? ex2(SC[n][0]) : 0.f;
                const float p01 = (key + 1 <= q0 && pad1 == 0.f) ? ex2(SC[n][1]) : 0.f;
                const float p10 = (key     <= q1 && pad0 == 0.f) ? ex2(SC[n][2]) : 0.f;
                const float p11 = (key + 1 <= q1 && pad1 == 0.f) ? ex2(SC[n][3]) : 0.f;
                const uint32_t hA = cvt_f16x2(p01, p00);
                const uint32_t hB = cvt_f16x2(p11, p10);
                // accumulate the ROUNDED p so numerator/denominator errors cancel
                const float2 fA = __half22float2(*reinterpret_cast<const half2*>(&hA));
                const float2 fB = __half22float2(*reinterpret_cast<const half2*>(&hB));
                rs0 += fA.x + fA.y;
                rs1 += fB.x + fB.y;
                const int kc = n >> 1, sub = (n & 1) * 2;
                Ph[kc][sub] = hA; Ph[kc][sub + 1] = hB;
            }

            // ---- O += P V (V via ldmatrix.trans) ----
            {
                const int vrow0 = kb0 + (g8 & 1) * 8 + l8;
                #pragma unroll
                for (int kc = 0; kc < 4; kc++) {
                    #pragma unroll
                    for (int ndp = 0; ndp < 4; ndp++) {
                        const int row = vrow0 + kc * 16;
                        const int c = 2 * ndp + (g8 >> 1);
                        uint32_t bh[4];
                        ldm_x4_t(bh, stb + OFF_V + row * 128 + (((uint32_t)(c ^ (row & 7))) << 4));
                        mma_f16(OC[2*ndp],   Ph[kc], bh);
                        mma_f16(OC[2*ndp+1], Ph[kc], bh + 2);
                    }
                }
            }

            if (j + 1 < nkt) CP_WAIT0();
            __syncthreads();
        }

        // ---- merge the two key-halves (ADD; no rescaling needed) ----
        rs0 += __shfl_xor_sync(0xFFFFFFFFu, rs0, 1);
        rs0 += __shfl_xor_sync(0xFFFFFFFFu, rs0, 2);
        rs1 += __shfl_xor_sync(0xFFFFFFFFu, rs1, 1);
        rs1 += __shfl_xor_sync(0xFFFFFFFFu, rs1, 2);
        if (lq == 0) {
            lsm[wc * 64 + wr * 16 + l4]     = rs0;
            lsm[wc * 64 + wr * 16 + 8 + l4] = rs1;
        }
        if (wc == 1) {
            const int r0 = wr * 16 + l4;
            #pragma unroll
            for (int nd = 0; nd < 8; nd++) {
                const int d0 = nd * 8 + 2 * lq;
                *reinterpret_cast<float2*>(&mrg[r0 * 64 + d0])       = make_float2(OC[nd][0], OC[nd][1]);
                *reinterpret_cast<float2*>(&mrg[(r0 + 8) * 64 + d0]) = make_float2(OC[nd][2], OC[nd][3]);
            }
        }
        __syncthreads();
        if (wc == 0) {
            const int r0 = wr * 16 + l4;
            const float lt0 = lsm[r0] + lsm[64 + r0];
            const float lt1 = lsm[r0 + 8] + lsm[64 + r0 + 8];
            const bool am0 = (lt0 == 0.f), am1 = (lt1 == 0.f);
            const float inv0 = am0 ? 0.f : 1.f / lt0;
            const float inv1 = am1 ? 0.f : 1.f / lt1;
            const int qr0 = qbase + r0, qr1 = qr0 + 8;
            #pragma unroll
            for (int nd = 0; nd < 8; nd++) {
                const int d0 = nd * 8 + 2 * lq;
                const float2 m0v = *reinterpret_cast<const float2*>(&mrg[r0 * 64 + d0]);
                const float2 m1v = *reinterpret_cast<const float2*>(&mrg[(r0 + 8) * 64 + d0]);
                float2 o0, o1;
                if (am0) o0 = make_float2(g_meanV[b * 64 + d0], g_meanV[b * 64 + d0 + 1]);
                else     o0 = make_float2((OC[nd][0] + m0v.x) * inv0, (OC[nd][1] + m0v.y) * inv0);
                if (am1) o1 = make_float2(g_meanV[b * 64 + d0], g_meanV[b * 64 + d0 + 1]);
                else     o1 = make_float2((OC[nd][2] + m1v.x) * inv1, (OC[nd][3] + m1v.y) * inv1);
                *reinterpret_cast<float2*>(&out[((size_t)b * S_ + qr0) * D_ + d0]) = o0;
                *reinterpret_cast<float2*>(&out[((size_t)b * S_ + qr1) * D_ + d0]) = o1;
            }
        }
    }
}

// ---------------------------------------------------------------------------
extern "C" void kernel_launch(void* const* d_in, const int* in_sizes, int n_in,
                              void* d_out, int out_size)
{
    const float* E  = (const float*)d_in[0];
    const float* PK = (const float*)d_in[1];
    const float* PV = (const float*)d_in[2];
    const float* Wq = (const float*)d_in[3];
    const float* bq = (const float*)d_in[4];
    const float* Wk = (const float*)d_in[5];
    const float* bk = (const float*)d_in[6];
    const float* Wv = (const float*)d_in[7];
    const float* bv = (const float*)d_in[8];
    const void*  pad = d_in[9];
    float* out = (float*)d_out;

    cudaFuncSetAttribute(attn_mma_kernel, cudaFuncAttributeMaxDynamicSharedMemorySize, SM_TOTAL);

    detect_pad_kernel<<<1, 1024>>>((const unsigned char*)pad);
    proj_kernel<<<B_ * S_ / 128, 128>>>(E, PK, PV, Wq, bq, Wk, bk, Wv, bv);
    meanv1_kernel<<<64, 256>>>();
    meanv2_kernel<<<1, 256>>>();
    attn_mma_kernel<<<dim3(32, B_), 256, SM_TOTAL>>>(pad, out);
}

// round 8
// speedup vs baseline: 8.8084x; 1.1920x over previous
#include <cuda_runtime.h>
#include <cuda_fp16.h>
#include <math.h>
#include <stdint.h>

// Problem constants
constexpr int B_ = 4, S_ = 4096, D_ = 64;
constexpr int MT = 64;            // q rows per tile (one phase)
constexpr int NT = 128;           // keys per k-tile
constexpr float QSCALE = 0.18033688011112042f;  // 0.125 * log2(e), folded into Q

// ---- global scratch (allocation-free rule) ----
__device__ __align__(16) __half g_Qh[B_*S_*D_];
__device__ __align__(16) __half g_Kh[B_*S_*D_];
__device__ __align__(16) __half g_Vh[B_*S_*D_];
__device__ __align__(16) float g_padneg[B_*S_];   // 0.0 (keep) or -inf (masked)
__device__ float g_part[128][D_];
__device__ float g_meanV[B_*D_];

// ---- f32x2 helpers (proj kernel) ----
using u64_t = unsigned long long;
__device__ __forceinline__ u64_t fma2(u64_t a, u64_t b, u64_t c) {
    u64_t d; asm("fma.rn.f32x2 %0, %1, %2, %3;" : "=l"(d) : "l"(a), "l"(b), "l"(c)); return d;
}
__device__ __forceinline__ float2 unpack2(u64_t v) {
    float2 r; asm("mov.b64 {%0, %1}, %2;" : "=f"(r.x), "=f"(r.y) : "l"(v)); return r;
}

__device__ __forceinline__ uint32_t smem_u32(const void* p) {
    uint32_t a;
    asm("{ .reg .u64 t; cvta.to.shared.u64 t, %1; cvt.u32.u64 %0, t; }" : "=r"(a) : "l"(p));
    return a;
}

// ---- mma.sync / ldmatrix / misc PTX ----
__device__ __forceinline__ void ldm_x4(uint32_t* r, uint32_t a) {
    asm volatile("ldmatrix.sync.aligned.m8n8.x4.shared.b16 {%0,%1,%2,%3}, [%4];"
                 : "=r"(r[0]), "=r"(r[1]), "=r"(r[2]), "=r"(r[3]) : "r"(a));
}
__device__ __forceinline__ void ldm_x4_t(uint32_t* r, uint32_t a) {
    asm volatile("ldmatrix.sync.aligned.m8n8.x4.trans.shared.b16 {%0,%1,%2,%3}, [%4];"
                 : "=r"(r[0]), "=r"(r[1]), "=r"(r[2]), "=r"(r[3]) : "r"(a));
}
__device__ __forceinline__ void mma_f16(float* c, const uint32_t* a, const uint32_t* b) {
    asm volatile("mma.sync.aligned.m16n8k16.row.col.f32.f16.f16.f32 "
                 "{%0,%1,%2,%3}, {%4,%5,%6,%7}, {%8,%9}, {%0,%1,%2,%3};"
                 : "+f"(c[0]), "+f"(c[1]), "+f"(c[2]), "+f"(c[3])
                 : "r"(a[0]), "r"(a[1]), "r"(a[2]), "r"(a[3]), "r"(b[0]), "r"(b[1]));
}
__device__ __forceinline__ float ex2(float x) {
    float y; asm("ex2.approx.f32 %0, %1;" : "=f"(y) : "f"(x)); return y;
}
// pack two fp32 -> fp16x2; second arg lands in the LOW half
__device__ __forceinline__ uint32_t cvt_f16x2(float hi, float lo) {
    uint32_t r; asm("cvt.rn.f16x2.f32 %0, %1, %2;" : "=r"(r) : "f"(hi), "f"(lo)); return r;
}
__device__ __forceinline__ void cpa16(uint32_t dst, const void* src) {
    asm volatile("cp.async.cg.shared.global [%0], [%1], 16;" :: "r"(dst), "l"(src));
}
#define CP_COMMIT() asm volatile("cp.async.commit_group;" ::: "memory")
#define CP_WAIT0()  asm volatile("cp.async.wait_group 0;" ::: "memory")

// ---------------------------------------------------------------------------
// Kernel 0: detect pad_mask dtype (scan first 16384 bytes = min buffer size),
// then emit canonical float mask: 0.0 = keep, -inf = masked.
// ---------------------------------------------------------------------------
__global__ void detect_pad_kernel(const void* __restrict__ pv)
{
    const unsigned char* p = (const unsigned char*)pv;
    __shared__ int f[2];
    const int t = threadIdx.x;
    if (t < 2) f[t] = 0;
    __syncthreads();
    int ge2 = 0, odd = 0;
    for (int i = t; i < B_ * S_; i += blockDim.x) {
        unsigned v = p[i];
        if (v >= 2u) ge2 = 1;
        if ((i & 3) && v) odd = 1;
    }
    if (ge2) atomicOr(&f[0], 1);
    if (odd) atomicOr(&f[1], 1);
    __syncthreads();
    const int kind = f[0] ? 2 : (f[1] ? 0 : 1);   // 0=u8, 1=i32, 2=f32
    const float NEGINF = __int_as_float(0xff800000);
    for (int i = t; i < B_ * S_; i += blockDim.x) {
        bool m;
        if (kind == 0)      m = p[i] != 0;
        else if (kind == 1) m = ((const int*)pv)[i] != 0;
        else                m = ((const float*)pv)[i] != 0.f;
        g_padneg[i] = m ? NEGINF : 0.f;
    }
}

// ---------------------------------------------------------------------------
// Kernel 1: fused QKV projection + popularity modulation -> single fp16,
// plus per-block V_p column sums (meanV partials). 128 blocks x 128 threads.
// ---------------------------------------------------------------------------
__global__ __launch_bounds__(128) void proj_kernel(
    const float* __restrict__ E,  const float* __restrict__ PK, const float* __restrict__ PV,
    const float* __restrict__ Wq, const float* __restrict__ bq,
    const float* __restrict__ Wk, const float* __restrict__ bk,
    const float* __restrict__ Wv, const float* __restrict__ bv)
{
    __shared__ float Wsm[3][D_ * D_];     // 48 KB; reused as reduction scratch
    const int t = threadIdx.x;
    const size_t g = (size_t)blockIdx.x * 128 + t;

    {
        const float* Ws[3] = {Wq, Wk, Wv};
        #pragma unroll
        for (int m = 0; m < 3; m++) {
            float4* dst = reinterpret_cast<float4*>(Wsm[m]);
            const float4* src = reinterpret_cast<const float4*>(Ws[m]);
            #pragma unroll
            for (int i = 0; i < 8; i++) dst[t + i * 128] = src[t + i * 128];
        }
    }
    __syncthreads();

    u64_t e2[32];
    {
        const ulonglong2* er = reinterpret_cast<const ulonglong2*>(E + g * D_);
        #pragma unroll
        for (int i = 0; i < 16; i++) { ulonglong2 v = er[i]; e2[2*i] = v.x; e2[2*i+1] = v.y; }
    }

    const float* bsx[3] = {bq, bk, bv};
    __half* oh3[3] = {g_Qh, g_Kh, g_Vh};
    float outv[D_];

    #pragma unroll
    for (int m = 0; m < 3; m++) {
        for (int c = 0; c < D_; c++) {
            const ulonglong2* wr = reinterpret_cast<const ulonglong2*>(Wsm[m] + c * D_);
            u64_t a0 = 0ull, a1 = 0ull;
            #pragma unroll
            for (int d8 = 0; d8 < 16; d8++) {
                ulonglong2 w = wr[d8];
                a0 = fma2(e2[2*d8],   w.x, a0);
                a1 = fma2(e2[2*d8+1], w.y, a1);
            }
            float2 p0 = unpack2(a0), p1 = unpack2(a1);
            outv[c] = bsx[m][c] + ((p0.x + p0.y) + (p1.x + p1.y));
        }
        if (m == 0) {
            #pragma unroll
            for (int c = 0; c < D_; c++) outv[c] *= QSCALE;
        } else {
            const float* mod = (m == 1 ? PK : PV) + g * D_;
            #pragma unroll
            for (int c = 0; c < D_; c++) outv[c] *= mod[c];
        }
        unsigned short hb[D_];
        #pragma unroll
        for (int c = 0; c < D_; c++)
            hb[c] = __half_as_ushort(__float2half_rn(outv[c]));
        uint4* oh = reinterpret_cast<uint4*>(oh3[m] + g * D_);
        const uint4* sh = reinterpret_cast<const uint4*>(hb);
        #pragma unroll
        for (int i = 0; i < 8; i++) oh[i] = sh[i];
    }

    // ---- meanV partial: outv currently holds this row's fp32 V_p ----
    __syncthreads();                       // everyone done reading Wsm
    float* red = Wsm[0];                   // 128 x 64 f32 = 32 KB (Wsm[0..1])
    #pragma unroll
    for (int i = 0; i < 16; i++)
        reinterpret_cast<float4*>(red + t * 64)[i] =
            make_float4(outv[4*i], outv[4*i+1], outv[4*i+2], outv[4*i+3]);
    __syncthreads();
    {
        const int col = t & 63, hf = t >> 6;
        float a = 0.f;
        #pragma unroll 8
        for (int r = hf * 64; r < hf * 64 + 64; r++) a += red[r * 64 + col];
        float* comb = Wsm[2];
        comb[t] = a;
        __syncthreads();
        if (t < 64)
            g_part[blockIdx.x][t] = comb[t] + comb[t + 64];
    }
}

// ---------------------------------------------------------------------------
// Kernel 2: finalize per-batch mean of V_p (fallback for fully-masked rows)
// ---------------------------------------------------------------------------
__global__ void meanv2_kernel()
{
    const int t = threadIdx.x;             // 256
    const int b = t >> 6, d = t & 63;
    float a = 0.f;
    #pragma unroll
    for (int i = 0; i < 32; i++) a += g_part[b * 32 + i][d];
    g_meanV[b * 64 + d] = a * (1.0f / (float)S_);
}

// ---------------------------------------------------------------------------
// Kernel 3: single-fp16 mma.sync flash attention, cp.async double-buffered.
// CTA = 256 threads = 4 row-warps x 2 key-halves over a 64-row q-tile.
// Pair scheduling (qt, 63-qt): exactly 33 k-tiles per CTA.
// Pad mask is a canonical additive -inf/0 float; only the LAST k-tile of a
// phase straddles the causal diagonal, so interior tiles skip causal checks.
// ---------------------------------------------------------------------------
constexpr int SM_QH   = 0;                      // 64 x 128B
constexpr int SM_KV   = 8192;                   // 2 stages x (K 16KB + V 16KB)
constexpr int STG_SZ  = 32768;
constexpr int OFF_K   = 0, OFF_V = 16384;
constexpr int SM_PADB = SM_KV + 2 * STG_SZ;     // 73728, 2 x 512B
constexpr int SM_LSM  = SM_PADB + 1024;         // 74752, 2 x 64 f32
constexpr int SM_MRG  = SM_KV;                  // merge overlays stage 0 (drained)
constexpr int SM_TOTAL = SM_LSM + 512;          // 75264

__global__ __launch_bounds__(256, 1) void attn_mma_kernel(float* __restrict__ out)
{
    extern __shared__ char sm[];
    const uint32_t smb = smem_u32(sm);
    const int tid = threadIdx.x, wid = tid >> 5, lane = tid & 31;
    const int wr = wid & 3, wc = wid >> 2;        // row-warp, key-half
    const int b = blockIdx.y;
    const int g8 = lane >> 3, l8 = lane & 7, l4 = lane >> 2, lq = lane & 3;
    float* lsm  = reinterpret_cast<float*>(sm + SM_LSM);
    float* mrg  = reinterpret_cast<float*>(sm + SM_MRG);

    #pragma unroll 1
    for (int phase = 0; phase < 2; phase++) {
        const int qt = phase ? (63 - blockIdx.x) : blockIdx.x;
        const int qbase = qt * MT;
        const int nkt = (qt >> 1) + 1;

        __syncthreads();   // prev phase merge reads done; smem reusable

        // ---- prologue: async-copy Q + k-tile 0 into stage 0 ----
        {
            const uint4* qh4 = reinterpret_cast<const uint4*>(g_Qh + ((size_t)b * S_ + qbase) * D_);
            #pragma unroll
            for (int it = 0; it < 2; it++) {
                int i = tid + it * 256;            // 512 chunks
                int row = i >> 3, c = i & 7;
                uint32_t sw = row * 128 + (((uint32_t)(c ^ (row & 7))) << 4);
                cpa16(smb + SM_QH + sw, qh4 + i);
            }
            const __half* srcs[2] = {g_Kh + (size_t)b * S_ * D_, g_Vh + (size_t)b * S_ * D_};
            #pragma unroll
            for (int t2 = 0; t2 < 2; t2++) {
                #pragma unroll
                for (int it = 0; it < 4; it++) {
                    int i = tid + it * 256;        // 1024 chunks per tile
                    int row = i >> 3, c = i & 7;
                    uint32_t dst = smb + SM_KV + t2 * 16384 + row * 128 + (((uint32_t)(c ^ (row & 7))) << 4);
                    cpa16(dst, reinterpret_cast<const uint4*>(srcs[t2]) + i);
                }
            }
            if (tid < 32)
                cpa16(smb + SM_PADB + tid * 16, (const char*)(g_padneg + b * S_) + tid * 16);
            CP_COMMIT();
        }
        CP_WAIT0();
        __syncthreads();

        // ---- Q A-fragments, 4 d-chunks of 16 ----
        uint32_t qh[4][4];
        {
            const int row = wr * 16 + (g8 & 1) * 8 + l8;
            #pragma unroll
            for (int dc = 0; dc < 4; dc++) {
                const int c = 2 * dc + (g8 >> 1);
                ldm_x4(qh[dc], smb + SM_QH + row * 128 + (((uint32_t)(c ^ (row & 7))) << 4));
            }
        }

        float OC[8][4];
        #pragma unroll
        for (int i = 0; i < 8; i++)
            { OC[i][0] = 0.f; OC[i][1] = 0.f; OC[i][2] = 0.f; OC[i][3] = 0.f; }
        float rs0 = 0.f, rs1 = 0.f;
        const int q0 = qbase + wr * 16 + l4, q1 = q0 + 8;
        const int kb0 = wc * 64;

        #pragma unroll 1
        for (int j = 0; j < nkt; j++) {
            const int st = j & 1;
            const uint32_t stb = smb + SM_KV + st * STG_SZ;
            const float* padsm = reinterpret_cast<const float*>(sm + SM_PADB + st * 512);
            const int kt = j * NT;

            // issue copy for tile j+1 into the other stage (overlaps compute)
            if (j + 1 < nkt) {
                const int ktn = (j + 1) * NT;
                const uint32_t nstb = smb + SM_KV + ((j + 1) & 1) * STG_SZ;
                const __half* srcs[2] = {g_Kh + ((size_t)b * S_ + ktn) * D_,
                                         g_Vh + ((size_t)b * S_ + ktn) * D_};
                #pragma unroll
                for (int t2 = 0; t2 < 2; t2++) {
                    #pragma unroll
                    for (int it = 0; it < 4; it++) {
                        int i = tid + it * 256;
                        int row = i >> 3, c = i & 7;
                        uint32_t dst = nstb + t2 * 16384 + row * 128 + (((uint32_t)(c ^ (row & 7))) << 4);
                        cpa16(dst, reinterpret_cast<const uint4*>(srcs[t2]) + i);
                    }
                }
                if (tid < 32)
                    cpa16(smb + SM_PADB + ((j + 1) & 1) * 512 + tid * 16,
                          (const char*)(g_padneg + b * S_ + ktn) + tid * 16);
                CP_COMMIT();
            }

            // ---- S = Q K^T (single fp16) ----
            float SC[8][4];
            #pragma unroll
            for (int i = 0; i < 8; i++)
                { SC[i][0] = 0.f; SC[i][1] = 0.f; SC[i][2] = 0.f; SC[i][3] = 0.f; }
            {
                const int krow0 = kb0 + (g8 >> 1) * 8 + l8;
                #pragma unroll
                for (int dc = 0; dc < 4; dc++) {
                    #pragma unroll
                    for (int kp = 0; kp < 4; kp++) {
                        const int row = krow0 + kp * 16;
                        const int c = 2 * dc + (g8 & 1);
                        uint32_t bh[4];
                        ldm_x4(bh, stb + OFF_K + row * 128 + (((uint32_t)(c ^ (row & 7))) << 4));
                        mma_f16(SC[2*kp],   qh[dc], bh);
                        mma_f16(SC[2*kp+1], qh[dc], bh + 2);
                    }
                }
            }

            // ---- mask + ex2 + C->A fragment conversion ----
            uint32_t Ph[4][4];
            if (j < nkt - 1) {
                // interior tile: no causal check; mask folded as additive -inf/0
                #pragma unroll
                for (int n = 0; n < 8; n++) {
                    const int colb = kb0 + n * 8 + 2 * lq;
                    const float m0 = padsm[colb], m1 = padsm[colb + 1];
                    const float p00 = ex2(SC[n][0] + m0);
                    const float p01 = ex2(SC[n][1] + m1);
                    const float p10 = ex2(SC[n][2] + m0);
                    const float p11 = ex2(SC[n][3] + m1);
                    const uint32_t hA = cvt_f16x2(p01, p00);
                    const uint32_t hB = cvt_f16x2(p11, p10);
                    const float2 fA = __half22float2(*reinterpret_cast<const half2*>(&hA));
                    const float2 fB = __half22float2(*reinterpret_cast<const half2*>(&hB));
                    rs0 += fA.x + fA.y;
                    rs1 += fB.x + fB.y;
                    const int kc = n >> 1, sub = (n & 1) * 2;
                    Ph[kc][sub] = hA; Ph[kc][sub + 1] = hB;
                }
            } else {
                // diagonal tile: causal predicate active
                #pragma unroll
                for (int n = 0; n < 8; n++) {
                    const int colb = kb0 + n * 8 + 2 * lq;
                    const int key = kt + colb;
                    const float m0 = padsm[colb], m1 = padsm[colb + 1];
                    const float p00 = (key     <= q0) ? ex2(SC[n][0] + m0) : 0.f;
                    const float p01 = (key + 1 <= q0) ? ex2(SC[n][1] + m1) : 0.f;
                    const float p10 = (key     <= q1) ? ex2(SC[n][2] + m0) : 0.f;
                    const float p11 = (key + 1 <= q1) ? ex2(SC[n][3] + m1) : 0.f;
                    const uint32_t hA = cvt_f16x2(p01, p00);
                    const uint32_t hB = cvt_f16x2(p11, p10);
                    const float2 fA = __half22float2(*reinterpret_cast<const half2*>(&hA));
                    const float2 fB = __half22float2(*reinterpret_cast<const half2*>(&hB));
                    rs0 += fA.x + fA.y;
                    rs1 += fB.x + fB.y;
                    const int kc = n >> 1, sub = (n & 1) * 2;
                    Ph[kc][sub] = hA; Ph[kc][sub + 1] = hB;
                }
            }

            // ---- O += P V (V via ldmatrix.trans) ----
            {
                const int vrow0 = kb0 + (g8 & 1) * 8 + l8;
                #pragma unroll
                for (int kc = 0; kc < 4; kc++) {
                    #pragma unroll
                    for (int ndp = 0; ndp < 4; ndp++) {
                        const int row = vrow0 + kc * 16;
                        const int c = 2 * ndp + (g8 >> 1);
                        uint32_t bh[4];
                        ldm_x4_t(bh, stb + OFF_V + row * 128 + (((uint32_t)(c ^ (row & 7))) << 4));
                        mma_f16(OC[2*ndp],   Ph[kc], bh);
                        mma_f16(OC[2*ndp+1], Ph[kc], bh + 2);
                    }
                }
            }

            if (j + 1 < nkt) CP_WAIT0();
            __syncthreads();
        }

        // ---- merge the two key-halves (ADD; no rescaling needed) ----
        rs0 += __shfl_xor_sync(0xFFFFFFFFu, rs0, 1);
        rs0 += __shfl_xor_sync(0xFFFFFFFFu, rs0, 2);
        rs1 += __shfl_xor_sync(0xFFFFFFFFu, rs1, 1);
        rs1 += __shfl_xor_sync(0xFFFFFFFFu, rs1, 2);
        if (lq == 0) {
            lsm[wc * 64 + wr * 16 + l4]     = rs0;
            lsm[wc * 64 + wr * 16 + 8 + l4] = rs1;
        }
        if (wc == 1) {
            const int r0 = wr * 16 + l4;
            #pragma unroll
            for (int nd = 0; nd < 8; nd++) {
                const int d0 = nd * 8 + 2 * lq;
                *reinterpret_cast<float2*>(&mrg[r0 * 64 + d0])       = make_float2(OC[nd][0], OC[nd][1]);
                *reinterpret_cast<float2*>(&mrg[(r0 + 8) * 64 + d0]) = make_float2(OC[nd][2], OC[nd][3]);
            }
        }
        __syncthreads();
        if (wc == 0) {
            const int r0 = wr * 16 + l4;
            const float lt0 = lsm[r0] + lsm[64 + r0];
            const float lt1 = lsm[r0 + 8] + lsm[64 + r0 + 8];
            const bool am0 = (lt0 == 0.f), am1 = (lt1 == 0.f);
            const float inv0 = am0 ? 0.f : 1.f / lt0;
            const float inv1 = am1 ? 0.f : 1.f / lt1;
            const int qr0 = qbase + r0, qr1 = qr0 + 8;
            #pragma unroll
            for (int nd = 0; nd < 8; nd++) {
                const int d0 = nd * 8 + 2 * lq;
                const float2 m0v = *reinterpret_cast<const float2*>(&mrg[r0 * 64 + d0]);
                const float2 m1v = *reinterpret_cast<const float2*>(&mrg[(r0 + 8) * 64 + d0]);
                float2 o0, o1;
                if (am0) o0 = make_float2(g_meanV[b * 64 + d0], g_meanV[b * 64 + d0 + 1]);
                else     o0 = make_float2((OC[nd][0] + m0v.x) * inv0, (OC[nd][1] + m0v.y) * inv0);
                if (am1) o1 = make_float2(g_meanV[b * 64 + d0], g_meanV[b * 64 + d0 + 1]);
                else     o1 = make_float2((OC[nd][2] + m1v.x) * inv1, (OC[nd][3] + m1v.y) * inv1);
                *reinterpret_cast<float2*>(&out[((size_t)b * S_ + qr0) * D_ + d0]) = o0;
                *reinterpret_cast<float2*>(&out[((size_t)b * S_ + qr1) * D_ + d0]) = o1;
            }
        }
    }
}

// ---------------------------------------------------------------------------
extern "C" void kernel_launch(void* const* d_in, const int* in_sizes, int n_in,
                              void* d_out, int out_size)
{
    const float* E  = (const float*)d_in[0];
    const float* PK = (const float*)d_in[1];
    const float* PV = (const float*)d_in[2];
    const float* Wq = (const float*)d_in[3];
    const float* bq = (const float*)d_in[4];
    const float* Wk = (const float*)d_in[5];
    const float* bk = (const float*)d_in[6];
    const float* Wv = (const float*)d_in[7];
    const float* bv = (const float*)d_in[8];
    const void*  pad = d_in[9];
    float* out = (float*)d_out;

    cudaFuncSetAttribute(attn_mma_kernel, cudaFuncAttributeMaxDynamicSharedMemorySize, SM_TOTAL);

    detect_pad_kernel<<<1, 1024>>>(pad);
    proj_kernel<<<B_ * S_ / 128, 128>>>(E, PK, PV, Wq, bq, Wk, bk, Wv, bv);
    meanv2_kernel<<<1, 256>>>();
    attn_mma_kernel<<<dim3(32, B_), 256, SM_TOTAL>>>(out);
}